// round 6
// baseline (speedup 1.0000x reference)
#include <cuda_runtime.h>
#include <mma.h>
#include <math.h>

using namespace nvcuda;

#define Bb 2
#define Cc 320
#define Nn 1024
#define NHh 8
#define DHh 40
#define Ll 2
#define EPS 1e-5f
#define EDGE_SCALE 0.17677669529663687f
#define ATT_SCALE  0.15811388300841897f

__device__ float g_node[Bb * Nn * Cc];
__device__ float g_qk2[Bb * Nn * 2 * Cc];
__device__ float g_edge[Bb * Nn * Nn];
__device__ float g_s[Bb * Cc];
__device__ float g_y[Bb * Nn * Cc];
__device__ float g_qkv[Bb * Nn * 3 * Cc];
__device__ float g_attn[Bb * NHh * Nn * Nn];
__device__ float g_nodeout[Bb * Nn * Cc];

__device__ __forceinline__ float blockReduceSum(float v, float* sred) {
    #pragma unroll
    for (int o = 16; o > 0; o >>= 1) v += __shfl_xor_sync(0xffffffffu, v, o);
    int w = threadIdx.x >> 5;
    if ((threadIdx.x & 31) == 0) sred[w] = v;
    __syncthreads();
    int nw = blockDim.x >> 5;
    if (threadIdx.x < 32) {
        float x = (threadIdx.x < nw) ? sred[threadIdx.x] : 0.f;
        #pragma unroll
        for (int o = 16; o > 0; o >>= 1) x += __shfl_xor_sync(0xffffffffu, x, o);
        if (threadIdx.x == 0) sred[0] = x;
    }
    __syncthreads();
    float r = sred[0];
    __syncthreads();
    return r;
}

__device__ __forceinline__ float blockReduceMax(float v, float* sred) {
    #pragma unroll
    for (int o = 16; o > 0; o >>= 1) v = fmaxf(v, __shfl_xor_sync(0xffffffffu, v, o));
    int w = threadIdx.x >> 5;
    if ((threadIdx.x & 31) == 0) sred[w] = v;
    __syncthreads();
    int nw = blockDim.x >> 5;
    if (threadIdx.x < 32) {
        float x = (threadIdx.x < nw) ? sred[threadIdx.x] : -INFINITY;
        #pragma unroll
        for (int o = 16; o > 0; o >>= 1) x = fmaxf(x, __shfl_xor_sync(0xffffffffu, x, o));
        if (threadIdx.x == 0) sred[0] = x;
    }
    __syncthreads();
    float r = sred[0];
    __syncthreads();
    return r;
}

__global__ void transpose_in(const float* __restrict__ x) {
    __shared__ float tile[32][33];
    int b = blockIdx.z;
    int c0 = blockIdx.y * 32, n0 = blockIdx.x * 32;
    int tx = threadIdx.x, ty = threadIdx.y;
    tile[ty][tx] = x[(long)b * Cc * Nn + (long)(c0 + ty) * Nn + n0 + tx];
    __syncthreads();
    g_node[((long)b * Nn + n0 + ty) * Cc + c0 + tx] = tile[tx][ty];
}

__global__ void transpose_out(float* __restrict__ out) {
    __shared__ float tile[32][33];
    int b = blockIdx.z;
    int c0 = blockIdx.y * 32, n0 = blockIdx.x * 32;
    int tx = threadIdx.x, ty = threadIdx.y;
    tile[ty][tx] = g_node[((long)b * Nn + n0 + ty) * Cc + c0 + tx];
    __syncthreads();
    out[(long)b * Cc * Nn + (long)(c0 + ty) * Nn + n0 + tx] = tile[tx][ty];
}

// TF32 WMMA NT GEMM: C = alpha*A@W^T + bias. Block 128x64, K-tile 32.
__global__ void gemm_tf32(const float* __restrict__ A, const float* __restrict__ W,
                          const float* __restrict__ bias, float* __restrict__ C,
                          int M, int Ncols, int K, int lda, int ldw, int ldc,
                          long sA, long sW, long sC, float alpha) {
    __shared__ float sbuf[8704];
    float (*As)[36] = (float(*)[36])sbuf;
    float (*Ws)[36] = (float(*)[36])(sbuf + 128 * 36);
    int z = blockIdx.z;
    A += (long)z * sA; W += (long)z * sW; C += (long)z * sC;
    int bm = blockIdx.y * 128, bn = blockIdx.x * 64;
    int tid = threadIdx.x;
    int w = tid >> 5;
    int wm = w >> 1, wn = w & 1;
    wmma::fragment<wmma::accumulator, 16, 16, 8, float> c[2][2];
    #pragma unroll
    for (int i = 0; i < 2; i++)
        #pragma unroll
        for (int j = 0; j < 2; j++) wmma::fill_fragment(c[i][j], 0.f);
    for (int k0 = 0; k0 < K; k0 += 32) {
        #pragma unroll
        for (int i = 0; i < 4; i++) {
            int idx = tid + i * 256;
            int r = idx >> 3, c4 = (idx & 7) * 4;
            *(float4*)&As[r][c4] = *(const float4*)&A[(long)(bm + r) * lda + k0 + c4];
        }
        #pragma unroll
        for (int i = 0; i < 2; i++) {
            int idx = tid + i * 256;
            int r = idx >> 3, c4 = (idx & 7) * 4;
            *(float4*)&Ws[r][c4] = *(const float4*)&W[(long)(bn + r) * ldw + k0 + c4];
        }
        __syncthreads();
        #pragma unroll
        for (int kk = 0; kk < 4; kk++) {
            wmma::fragment<wmma::matrix_a, 16, 16, 8, wmma::precision::tf32, wmma::row_major> a[2];
            wmma::fragment<wmma::matrix_b, 16, 16, 8, wmma::precision::tf32, wmma::col_major> bf[2];
            #pragma unroll
            for (int i = 0; i < 2; i++) {
                wmma::load_matrix_sync(a[i], &As[wm * 32 + i * 16][kk * 8], 36);
                #pragma unroll
                for (int e = 0; e < a[i].num_elements; e++) a[i].x[e] = wmma::__float_to_tf32(a[i].x[e]);
            }
            #pragma unroll
            for (int j = 0; j < 2; j++) {
                wmma::load_matrix_sync(bf[j], &Ws[wn * 32 + j * 16][kk * 8], 36);
                #pragma unroll
                for (int e = 0; e < bf[j].num_elements; e++) bf[j].x[e] = wmma::__float_to_tf32(bf[j].x[e]);
            }
            #pragma unroll
            for (int i = 0; i < 2; i++)
                #pragma unroll
                for (int j = 0; j < 2; j++) wmma::mma_sync(c[i][j], a[i], bf[j], c[i][j]);
        }
        __syncthreads();
    }
    #pragma unroll
    for (int i = 0; i < 2; i++)
        #pragma unroll
        for (int j = 0; j < 2; j++) {
            #pragma unroll
            for (int e = 0; e < c[i][j].num_elements; e++) c[i][j].x[e] *= alpha;
            wmma::store_matrix_sync(&sbuf[(wm * 32 + i * 16) * 68 + wn * 32 + j * 16],
                                    c[i][j], 68, wmma::mem_row_major);
        }
    __syncthreads();
    #pragma unroll
    for (int i = 0; i < 8; i++) {
        int idx = tid + i * 256;
        int r = idx >> 4, c4 = (idx & 15) * 4;
        float4 v = *(float4*)&sbuf[r * 68 + c4];
        if (bias) {
            float4 bb = *(const float4*)&bias[bn + c4];
            v.x += bb.x; v.y += bb.y; v.z += bb.z; v.w += bb.w;
        }
        *(float4*)&C[(long)(bm + r) * ldc + bn + c4] = v;
    }
}

__global__ void edge_softmax(void) {
    __shared__ float sred[32];
    long row = blockIdx.x;
    float* p = g_edge + row * Nn;
    int tid = threadIdx.x;
    float4 r = *(float4*)&p[tid * 4];
    float lmax = fmaxf(fmaxf(r.x, r.y), fmaxf(r.z, r.w));
    float smax = blockReduceMax(lmax, sred);
    r.x = __expf(r.x - smax); r.y = __expf(r.y - smax);
    r.z = __expf(r.z - smax); r.w = __expf(r.w - smax);
    float Z = blockReduceSum(r.x + r.y + r.z + r.w, sred);
    float inv = 1.f / Z;
    r.x *= inv; r.y *= inv; r.z *= inv; r.w *= inv;
    *(float4*)&p[tid * 4] = r;
}

__global__ void fcp_kernel(const float* __restrict__ da, const float* __restrict__ fw,
                           const float* __restrict__ fb) {
    __shared__ float t[64];
    int b = blockIdx.x;
    int tid = threadIdx.x;
    if (tid < 64) {
        float s = 0.f;
        #pragma unroll
        for (int a = 0; a < 16; a++) s += da[(long)b * 16 * 64 + a * 64 + tid];
        t[tid] = s;
    }
    __syncthreads();
    float s = 16.f * fb[tid];
    #pragma unroll
    for (int e = 0; e < 64; e++) s += t[e] * fw[tid * 64 + e];
    g_s[b * Cc + tid] = s;
}

__global__ void norm_kernel(const float* __restrict__ g1, const float* __restrict__ b1,
                            const float* __restrict__ g2, const float* __restrict__ b2) {
    __shared__ float sred[32];
    int bn = blockIdx.x;
    int b = bn >> 10, n = bn & 1023;
    int c = threadIdx.x;
    float x = g_node[(long)bn * Cc + c];
    float mean = blockReduceSum(x, sred) * (1.f / Cc);
    float d = x - mean;
    float var = blockReduceSum(d * d, sred) * (1.f / Cc);
    float nt = d * rsqrtf(var + EPS) * g1[c] + b1[c];
    float diag = g_edge[(long)b * Nn * Nn + (long)n * Nn + n];
    float v2 = diag * nt * g_s[b * Cc + c] + nt;
    float mean2 = blockReduceSum(v2, sred) * (1.f / Cc);
    float dd = v2 - mean2;
    float var2 = blockReduceSum(dd * dd, sred) * (1.f / Cc);
    g_y[(long)bn * Cc + c] = dd * rsqrtf(var2 + EPS) * g2[c] + b2[c];
}

// attn scores (TF32 WMMA): S = QK^T*scale + edge*ew + eb -> g_attn (raw scores)
__global__ void attn_score_tf32(const float* __restrict__ exp_w, const float* __restrict__ exp_b) {
    __shared__ float sb[5632];
    float (*Qs)[44] = (float(*)[44])sb;
    float (*Ks)[44] = (float(*)[44])(sb + 64 * 44);
    int bh = blockIdx.z;
    int b = bh >> 3, h = bh & 7;
    int n0 = blockIdx.y * 64, m0 = blockIdx.x * 64;
    const float* Qb = g_qkv + (long)b * Nn * 960 + h * DHh;
    const float* Kb = Qb + Cc;
    int tid = threadIdx.x;
    for (int idx = tid; idx < 640; idx += 256) {
        int r = idx / 10, c4 = (idx % 10) * 4;
        *(float4*)&Qs[r][c4] = *(const float4*)&Qb[(long)(n0 + r) * 960 + c4];
        *(float4*)&Ks[r][c4] = *(const float4*)&Kb[(long)(m0 + r) * 960 + c4];
    }
    __syncthreads();
    int w = tid >> 5, wr = w >> 1, wc = w & 1;
    wmma::fragment<wmma::accumulator, 16, 16, 8, float> c[2];
    wmma::fill_fragment(c[0], 0.f);
    wmma::fill_fragment(c[1], 0.f);
    #pragma unroll
    for (int kk = 0; kk < 5; kk++) {
        wmma::fragment<wmma::matrix_a, 16, 16, 8, wmma::precision::tf32, wmma::row_major> a;
        wmma::load_matrix_sync(a, &Qs[wr * 16][kk * 8], 44);
        #pragma unroll
        for (int e = 0; e < a.num_elements; e++) a.x[e] = wmma::__float_to_tf32(a.x[e]);
        #pragma unroll
        for (int j = 0; j < 2; j++) {
            wmma::fragment<wmma::matrix_b, 16, 16, 8, wmma::precision::tf32, wmma::col_major> bf;
            wmma::load_matrix_sync(bf, &Ks[wc * 32 + j * 16][kk * 8], 44);
            #pragma unroll
            for (int e = 0; e < bf.num_elements; e++) bf.x[e] = wmma::__float_to_tf32(bf.x[e]);
            wmma::mma_sync(c[j], a, bf, c[j]);
        }
    }
    __syncthreads();
    #pragma unroll
    for (int j = 0; j < 2; j++) {
        #pragma unroll
        for (int e = 0; e < c[j].num_elements; e++) c[j].x[e] *= ATT_SCALE;
        wmma::store_matrix_sync(&sb[(wr * 16) * 68 + wc * 32 + j * 16], c[j], 68,
                                wmma::mem_row_major);
    }
    __syncthreads();
    float ew = exp_w[h], eb = exp_b[h];
    const float* ep = g_edge + (long)b * Nn * Nn;
    float* op = g_attn + ((long)b * NHh + h) * Nn * Nn;
    #pragma unroll
    for (int i = 0; i < 4; i++) {
        int idx = tid + i * 256;
        int r = idx >> 4, c4 = (idx & 15) * 4;
        float4 s = *(float4*)&sb[r * 68 + c4];
        float4 e = *(const float4*)&ep[(long)(n0 + r) * Nn + m0 + c4];
        s.x += e.x * ew + eb; s.y += e.y * ew + eb;
        s.z += e.z * ew + eb; s.w += e.w * ew + eb;
        *(float4*)&op[(long)(n0 + r) * Nn + m0 + c4] = s;
    }
}

__device__ __forceinline__ void mergeTriple(float& m, float& z, float& s,
                                            float mo, float zo, float so) {
    float nm = fmaxf(m, mo);
    float f1 = __expf(m - nm), f2 = __expf(mo - nm);
    z = z * f1 + zo * f2;
    s = s * f1 + so * f2;
    m = nm;
}

__device__ __forceinline__ unsigned f2tf(float x) {
    return __float_as_uint(wmma::__float_to_tf32(x));
}
__device__ __forceinline__ void mma8(float* c, const unsigned* a, const unsigned* b) {
    asm volatile("mma.sync.aligned.m16n8k8.row.col.f32.tf32.tf32.f32 "
                 "{%0,%1,%2,%3}, {%4,%5,%6,%7}, {%8,%9}, {%0,%1,%2,%3};\n"
                 : "+f"(c[0]), "+f"(c[1]), "+f"(c[2]), "+f"(c[3])
                 : "r"(a[0]), "r"(a[1]), "r"(a[2]), "r"(a[3]), "r"(b[0]), "r"(b[1]));
}

// Fused: head-softmax stats + probs-in-registers AV + edge_new + edge update + wsum + out.
// grid (Nn/16, Bb), 256 threads, warp = head. Reads RAW scores from g_attn (L2-hot).
#define SMEM_EDAV 119872
__global__ void ednew_av(const float* __restrict__ red_w, const float* __restrict__ red_b) {
    extern __shared__ float sm[];
    float* Vs    = sm;            // [64][328] tf32-rounded V tile (all heads)
    float* Ts    = sm + 20992;    // [8][16][68] rw*(a+r)
    float* mzs   = sm + 29696;    // [8][16][2]
    float* wsums = sm + 29952;    // [16]
    int n0 = blockIdx.x * 16;
    int b  = blockIdx.y;
    int tid = threadIdx.x;
    int h = tid >> 5, lane = tid & 31;
    const float* qkv = g_qkv + (long)b * Nn * 960;
    float* ep = g_edge + (long)b * Nn * Nn;
    const float* Ab = g_attn + (((long)b * NHh + h) * Nn + n0) * Nn;

    // phase A: per-row (M, 1/Z) for head h. lane -> (row=lane>>1, half=lane&1)
    {
        int row = lane >> 1, half = lane & 1;
        const float* rp = Ab + (long)row * Nn + half * 512;
        float mx = -INFINITY;
        for (int j0 = 0; j0 < 128; j0 += 8) {
            #pragma unroll
            for (int j = 0; j < 8; j++) {
                float4 v = *(const float4*)&rp[(j0 + j) * 4];
                mx = fmaxf(mx, fmaxf(fmaxf(v.x, v.y), fmaxf(v.z, v.w)));
            }
        }
        mx = fmaxf(mx, __shfl_xor_sync(0xffffffffu, mx, 1));
        float z = 0.f;
        for (int j0 = 0; j0 < 128; j0 += 8) {
            #pragma unroll
            for (int j = 0; j < 8; j++) {
                float4 v = *(const float4*)&rp[(j0 + j) * 4];
                z += __expf(v.x - mx) + __expf(v.y - mx) + __expf(v.z - mx) + __expf(v.w - mx);
            }
        }
        z += __shfl_xor_sync(0xffffffffu, z, 1);
        if (half == 0) {
            mzs[(h * 16 + row) * 2] = mx;
            mzs[(h * 16 + row) * 2 + 1] = 1.f / z;
        }
    }
    __syncthreads();

    int g = lane >> 2, t = lane & 3;
    float M0 = mzs[(h * 16 + g) * 2],     iZ0 = mzs[(h * 16 + g) * 2 + 1];
    float M1 = mzs[(h * 16 + g + 8) * 2], iZ1 = mzs[(h * 16 + g + 8) * 2 + 1];
    float rw = red_w[h], rb = red_b[0];
    const float* arow0 = Ab + (long)g * Nn;
    const float* arow1 = Ab + (long)(g + 8) * Nn;
    float acc[5][4] = {};
    float me = -INFINITY, ze = 0.f, se = 0.f;
    int er = tid >> 4, ec = (tid & 15) * 4;

    for (int m0 = 0; m0 < Nn; m0 += 64) {
        float4 ecur = *(float4*)&ep[(long)(n0 + er) * Nn + m0 + ec];
        // V tile (64 x 320) -> smem, tf32-rounded at store
        for (int idx = tid; idx < 5120; idx += 256) {
            int r = idx / 80, c4 = (idx % 80) * 4;
            float4 v = *(const float4*)&qkv[(long)(m0 + r) * 960 + 640 + c4];
            v.x = wmma::__float_to_tf32(v.x); v.y = wmma::__float_to_tf32(v.y);
            v.z = wmma::__float_to_tf32(v.z); v.w = wmma::__float_to_tf32(v.w);
            *(float4*)&Vs[r * 328 + c4] = v;
        }
        __syncthreads();
        #pragma unroll
        for (int kk = 0; kk < 8; kk++) {
            int cb = m0 + kk * 8 + t;
            float s0 = arow0[cb], s1 = arow1[cb], s2 = arow0[cb + 4], s3 = arow1[cb + 4];
            float a0 = __expf(s0 - M0) * iZ0;
            float a1 = __expf(s1 - M1) * iZ1;
            float a2 = __expf(s2 - M0) * iZ0;
            float a3 = __expf(s3 - M1) * iZ1;
            int c0 = kk * 8 + t;
            Ts[(h * 16 + g) * 68 + c0]         = rw * (a0 + s0);
            Ts[(h * 16 + g + 8) * 68 + c0]     = rw * (a1 + s1);
            Ts[(h * 16 + g) * 68 + c0 + 4]     = rw * (a2 + s2);
            Ts[(h * 16 + g + 8) * 68 + c0 + 4] = rw * (a3 + s3);
            unsigned af[4] = {f2tf(a0), f2tf(a1), f2tf(a2), f2tf(a3)};
            #pragma unroll
            for (int nb = 0; nb < 5; nb++) {
                unsigned bf[2];
                bf[0] = __float_as_uint(Vs[(kk * 8 + t) * 328 + h * 40 + nb * 8 + g]);
                bf[1] = __float_as_uint(Vs[(kk * 8 + t + 4) * 328 + h * 40 + nb * 8 + g]);
                mma8(acc[nb], af, bf);
            }
        }
        __syncthreads();
        // cross-head edge_new, edge update, online wsum
        float4 en = {rb, rb, rb, rb};
        #pragma unroll
        for (int h2 = 0; h2 < 8; h2++) {
            float4 tv = *(float4*)&Ts[(h2 * 16 + er) * 68 + ec];
            en.x += tv.x; en.y += tv.y; en.z += tv.z; en.w += tv.w;
        }
        ecur.x += en.x; ecur.y += en.y; ecur.z += en.z; ecur.w += en.w;
        *(float4*)&ep[(long)(n0 + er) * Nn + m0 + ec] = ecur;
        float lm = fmaxf(fmaxf(en.x, en.y), fmaxf(en.z, en.w));
        float e0 = __expf(en.x - lm), e1 = __expf(en.y - lm),
              e2 = __expf(en.z - lm), e3 = __expf(en.w - lm);
        mergeTriple(me, ze, se, lm, e0 + e1 + e2 + e3,
                    e0 * en.x + e1 * en.y + e2 * en.z + e3 * en.w);
        __syncthreads();
    }
    // wsum: reduce 16 threads per row (16-lane halves; xor offsets stay in-half)
    #pragma unroll
    for (int o = 8; o > 0; o >>= 1)
        mergeTriple(me, ze, se,
                    __shfl_xor_sync(0xffffffffu, me, o),
                    __shfl_xor_sync(0xffffffffu, ze, o),
                    __shfl_xor_sync(0xffffffffu, se, o));
    if ((tid & 15) == 0) wsums[er] = se / ze;
    __syncthreads();
    float w0 = wsums[g], w1 = wsums[g + 8];
    float* op = g_nodeout + ((long)b * Nn + n0) * Cc + h * DHh;
    #pragma unroll
    for (int nb = 0; nb < 5; nb++) {
        int c = nb * 8 + 2 * t;
        *(float2*)&op[(long)g * Cc + c]       = make_float2(acc[nb][0] + w0, acc[nb][1] + w0);
        *(float2*)&op[(long)(g + 8) * Cc + c] = make_float2(acc[nb][2] + w1, acc[nb][3] + w1);
    }
}

static float* sym(const void* s) {
    void* p = nullptr;
    cudaGetSymbolAddress(&p, s);
    return (float*)p;
}

extern "C" void kernel_launch(void* const* d_in, const int* in_sizes, int n_in,
                              void* d_out, int out_size) {
    const float* x        = (const float*)d_in[0];
    const float* da_prior = (const float*)d_in[1];
    const float* qk_w     = (const float*)d_in[2];
    const float* fcp_w    = (const float*)d_in[3];
    const float* fcp_b    = (const float*)d_in[4];
    const float* ln1_g    = (const float*)d_in[5];
    const float* ln1_b    = (const float*)d_in[6];
    const float* gln_g    = (const float*)d_in[7];
    const float* gln_b    = (const float*)d_in[8];
    const float* qkv_w    = (const float*)d_in[9];
    const float* qkv_b    = (const float*)d_in[10];
    const float* proj_w   = (const float*)d_in[11];
    const float* proj_b   = (const float*)d_in[12];
    const float* exp_w    = (const float*)d_in[13];
    const float* exp_b    = (const float*)d_in[14];
    const float* red_w    = (const float*)d_in[15];
    const float* red_b    = (const float*)d_in[16];
    float* out = (float*)d_out;

    float* p_node    = sym(g_node);
    float* p_qk2     = sym(g_qk2);
    float* p_edge    = sym(g_edge);
    float* p_y       = sym(g_y);
    float* p_qkv     = sym(g_qkv);
    float* p_nodeout = sym(g_nodeout);

    cudaFuncSetAttribute(ednew_av, cudaFuncAttributeMaxDynamicSharedMemorySize, SMEM_EDAV);

    transpose_in<<<dim3(32, 10, Bb), dim3(32, 32)>>>(x);
    gemm_tf32<<<dim3(10, 16, 1), 256>>>(p_node, qk_w, nullptr, p_qk2,
                                        Bb * Nn, 2 * Cc, Cc, Cc, Cc, 2 * Cc, 0, 0, 0, 1.f);
    gemm_tf32<<<dim3(16, 8, Bb), 256>>>(p_qk2, p_qk2 + Cc, nullptr, p_edge,
                                        Nn, Nn, Cc, 2 * Cc, 2 * Cc, Nn,
                                        (long)Nn * 2 * Cc, (long)Nn * 2 * Cc, (long)Nn * Nn,
                                        EDGE_SCALE);
    edge_softmax<<<Bb * Nn, 256>>>();
    fcp_kernel<<<Bb, Cc>>>(da_prior, fcp_w, fcp_b);

    for (int l = 0; l < Ll; l++) {
        norm_kernel<<<Bb * Nn, Cc>>>(ln1_g + l * Cc, ln1_b + l * Cc,
                                     gln_g + l * Cc, gln_b + l * Cc);
        gemm_tf32<<<dim3(15, 16, 1), 256>>>(p_y, qkv_w + (long)l * 3 * Cc * Cc,
                                            qkv_b + l * 3 * Cc, p_qkv,
                                            Bb * Nn, 3 * Cc, Cc, Cc, Cc, 3 * Cc, 0, 0, 0, 1.f);
        attn_score_tf32<<<dim3(16, 16, Bb * NHh), 256>>>(exp_w + l * NHh, exp_b + l * NHh);
        ednew_av<<<dim3(64, Bb), 256, SMEM_EDAV>>>(red_w + l * NHh, red_b + l);
        gemm_tf32<<<dim3(5, 16, 1), 256>>>(p_nodeout, proj_w + (long)l * Cc * Cc,
                                           proj_b + l * Cc, p_node,
                                           Bb * Nn, Cc, Cc, Cc, Cc, Cc, 0, 0, 0, 1.f);
    }
    transpose_out<<<dim3(32, 10, Bb), dim3(32, 32)>>>(out);
}

// round 7
// speedup vs baseline: 1.6965x; 1.6965x over previous
#include <cuda_runtime.h>
#include <cuda_fp16.h>
#include <mma.h>
#include <math.h>

using namespace nvcuda;

#define Bb 2
#define Cc 320
#define Nn 1024
#define NHh 8
#define DHh 40
#define Ll 2
#define EPS 1e-5f
#define EDGE_SCALE 0.17677669529663687f
#define ATT_SCALE  0.15811388300841897f

__device__ float g_node[Bb * Nn * Cc];
__device__ float g_qk2[Bb * Nn * 2 * Cc];
__device__ float g_edge[Bb * Nn * Nn];
__device__ float g_s[Bb * Cc];
__device__ float g_y[Bb * Nn * Cc];
__device__ float g_qkv[Bb * Nn * 3 * Cc];
__device__ float g_attn[Bb * NHh * Nn * Nn];     // raw QK^T * scale (fp32)
__device__ __half g_probs[Bb * NHh * Nn * Nn];   // softmax probs (fp16)
__device__ float g_wsum[Bb * Nn];
__device__ float g_nodeout[Bb * Nn * Cc];

__device__ __forceinline__ float blockReduceSum(float v, float* sred) {
    #pragma unroll
    for (int o = 16; o > 0; o >>= 1) v += __shfl_xor_sync(0xffffffffu, v, o);
    int w = threadIdx.x >> 5;
    if ((threadIdx.x & 31) == 0) sred[w] = v;
    __syncthreads();
    int nw = blockDim.x >> 5;
    if (threadIdx.x < 32) {
        float x = (threadIdx.x < nw) ? sred[threadIdx.x] : 0.f;
        #pragma unroll
        for (int o = 16; o > 0; o >>= 1) x += __shfl_xor_sync(0xffffffffu, x, o);
        if (threadIdx.x == 0) sred[0] = x;
    }
    __syncthreads();
    float r = sred[0];
    __syncthreads();
    return r;
}

__device__ __forceinline__ float blockReduceMax(float v, float* sred) {
    #pragma unroll
    for (int o = 16; o > 0; o >>= 1) v = fmaxf(v, __shfl_xor_sync(0xffffffffu, v, o));
    int w = threadIdx.x >> 5;
    if ((threadIdx.x & 31) == 0) sred[w] = v;
    __syncthreads();
    int nw = blockDim.x >> 5;
    if (threadIdx.x < 32) {
        float x = (threadIdx.x < nw) ? sred[threadIdx.x] : -INFINITY;
        #pragma unroll
        for (int o = 16; o > 0; o >>= 1) x = fmaxf(x, __shfl_xor_sync(0xffffffffu, x, o));
        if (threadIdx.x == 0) sred[0] = x;
    }
    __syncthreads();
    float r = sred[0];
    __syncthreads();
    return r;
}

__global__ void transpose_in(const float* __restrict__ x) {
    __shared__ float tile[32][33];
    int b = blockIdx.z;
    int c0 = blockIdx.y * 32, n0 = blockIdx.x * 32;
    int tx = threadIdx.x, ty = threadIdx.y;
    tile[ty][tx] = x[(long)b * Cc * Nn + (long)(c0 + ty) * Nn + n0 + tx];
    __syncthreads();
    g_node[((long)b * Nn + n0 + ty) * Cc + c0 + tx] = tile[tx][ty];
}

__global__ void transpose_out(float* __restrict__ out) {
    __shared__ float tile[32][33];
    int b = blockIdx.z;
    int c0 = blockIdx.y * 32, n0 = blockIdx.x * 32;
    int tx = threadIdx.x, ty = threadIdx.y;
    tile[ty][tx] = g_node[((long)b * Nn + n0 + ty) * Cc + c0 + tx];
    __syncthreads();
    out[(long)b * Cc * Nn + (long)(c0 + ty) * Nn + n0 + tx] = tile[tx][ty];
}

// TF32 WMMA NT GEMM: C = alpha*A@W^T + bias. Block 128x64, K-tile 32.
__global__ void gemm_tf32(const float* __restrict__ A, const float* __restrict__ W,
                          const float* __restrict__ bias, float* __restrict__ C,
                          int M, int Ncols, int K, int lda, int ldw, int ldc,
                          long sA, long sW, long sC, float alpha) {
    __shared__ float sbuf[8704];
    float (*As)[36] = (float(*)[36])sbuf;
    float (*Ws)[36] = (float(*)[36])(sbuf + 128 * 36);
    int z = blockIdx.z;
    A += (long)z * sA; W += (long)z * sW; C += (long)z * sC;
    int bm = blockIdx.y * 128, bn = blockIdx.x * 64;
    int tid = threadIdx.x;
    int w = tid >> 5;
    int wm = w >> 1, wn = w & 1;
    wmma::fragment<wmma::accumulator, 16, 16, 8, float> c[2][2];
    #pragma unroll
    for (int i = 0; i < 2; i++)
        #pragma unroll
        for (int j = 0; j < 2; j++) wmma::fill_fragment(c[i][j], 0.f);
    for (int k0 = 0; k0 < K; k0 += 32) {
        #pragma unroll
        for (int i = 0; i < 4; i++) {
            int idx = tid + i * 256;
            int r = idx >> 3, c4 = (idx & 7) * 4;
            *(float4*)&As[r][c4] = *(const float4*)&A[(long)(bm + r) * lda + k0 + c4];
        }
        #pragma unroll
        for (int i = 0; i < 2; i++) {
            int idx = tid + i * 256;
            int r = idx >> 3, c4 = (idx & 7) * 4;
            *(float4*)&Ws[r][c4] = *(const float4*)&W[(long)(bn + r) * ldw + k0 + c4];
        }
        __syncthreads();
        #pragma unroll
        for (int kk = 0; kk < 4; kk++) {
            wmma::fragment<wmma::matrix_a, 16, 16, 8, wmma::precision::tf32, wmma::row_major> a[2];
            wmma::fragment<wmma::matrix_b, 16, 16, 8, wmma::precision::tf32, wmma::col_major> bf[2];
            #pragma unroll
            for (int i = 0; i < 2; i++) {
                wmma::load_matrix_sync(a[i], &As[wm * 32 + i * 16][kk * 8], 36);
                #pragma unroll
                for (int e = 0; e < a[i].num_elements; e++) a[i].x[e] = wmma::__float_to_tf32(a[i].x[e]);
            }
            #pragma unroll
            for (int j = 0; j < 2; j++) {
                wmma::load_matrix_sync(bf[j], &Ws[wn * 32 + j * 16][kk * 8], 36);
                #pragma unroll
                for (int e = 0; e < bf[j].num_elements; e++) bf[j].x[e] = wmma::__float_to_tf32(bf[j].x[e]);
            }
            #pragma unroll
            for (int i = 0; i < 2; i++)
                #pragma unroll
                for (int j = 0; j < 2; j++) wmma::mma_sync(c[i][j], a[i], bf[j], c[i][j]);
        }
        __syncthreads();
    }
    #pragma unroll
    for (int i = 0; i < 2; i++)
        #pragma unroll
        for (int j = 0; j < 2; j++) {
            #pragma unroll
            for (int e = 0; e < c[i][j].num_elements; e++) c[i][j].x[e] *= alpha;
            wmma::store_matrix_sync(&sbuf[(wm * 32 + i * 16) * 68 + wn * 32 + j * 16],
                                    c[i][j], 68, wmma::mem_row_major);
        }
    __syncthreads();
    #pragma unroll
    for (int i = 0; i < 8; i++) {
        int idx = tid + i * 256;
        int r = idx >> 4, c4 = (idx & 15) * 4;
        float4 v = *(float4*)&sbuf[r * 68 + c4];
        if (bias) {
            float4 bb = *(const float4*)&bias[bn + c4];
            v.x += bb.x; v.y += bb.y; v.z += bb.z; v.w += bb.w;
        }
        *(float4*)&C[(long)(bm + r) * ldc + bn + c4] = v;
    }
}

__global__ void edge_softmax(void) {
    __shared__ float sred[32];
    long row = blockIdx.x;
    float* p = g_edge + row * Nn;
    int tid = threadIdx.x;
    float4 r = *(float4*)&p[tid * 4];
    float lmax = fmaxf(fmaxf(r.x, r.y), fmaxf(r.z, r.w));
    float smax = blockReduceMax(lmax, sred);
    r.x = __expf(r.x - smax); r.y = __expf(r.y - smax);
    r.z = __expf(r.z - smax); r.w = __expf(r.w - smax);
    float Z = blockReduceSum(r.x + r.y + r.z + r.w, sred);
    float inv = 1.f / Z;
    r.x *= inv; r.y *= inv; r.z *= inv; r.w *= inv;
    *(float4*)&p[tid * 4] = r;
}

__global__ void fcp_kernel(const float* __restrict__ da, const float* __restrict__ fw,
                           const float* __restrict__ fb) {
    __shared__ float t[64];
    int b = blockIdx.x;
    int tid = threadIdx.x;
    if (tid < 64) {
        float s = 0.f;
        #pragma unroll
        for (int a = 0; a < 16; a++) s += da[(long)b * 16 * 64 + a * 64 + tid];
        t[tid] = s;
    }
    __syncthreads();
    float s = 16.f * fb[tid];
    #pragma unroll
    for (int e = 0; e < 64; e++) s += t[e] * fw[tid * 64 + e];
    g_s[b * Cc + tid] = s;
}

__global__ void norm_kernel(const float* __restrict__ g1, const float* __restrict__ b1,
                            const float* __restrict__ g2, const float* __restrict__ b2) {
    __shared__ float sred[32];
    int bn = blockIdx.x;
    int b = bn >> 10, n = bn & 1023;
    int c = threadIdx.x;
    float x = g_node[(long)bn * Cc + c];
    float mean = blockReduceSum(x, sred) * (1.f / Cc);
    float d = x - mean;
    float var = blockReduceSum(d * d, sred) * (1.f / Cc);
    float nt = d * rsqrtf(var + EPS) * g1[c] + b1[c];
    float diag = g_edge[(long)b * Nn * Nn + (long)n * Nn + n];
    float v2 = diag * nt * g_s[b * Cc + c] + nt;
    float mean2 = blockReduceSum(v2, sred) * (1.f / Cc);
    float dd = v2 - mean2;
    float var2 = blockReduceSum(dd * dd, sred) * (1.f / Cc);
    g_y[(long)bn * Cc + c] = dd * rsqrtf(var2 + EPS) * g2[c] + b2[c];
}

// attn scores (fp16 WMMA): writes RAW QK^T*ATT_SCALE to g_attn. One barrier.
__global__ void attn_score_half(void) {
    __shared__ __half Qs[64][48];
    __shared__ __half Ks[64][48];
    int bh = blockIdx.z;
    int b = bh >> 3, h = bh & 7;
    int n0 = blockIdx.y * 64, m0 = blockIdx.x * 64;
    const float* Qb = g_qkv + (long)b * Nn * 960 + h * DHh;
    const float* Kb = Qb + Cc;
    int tid = threadIdx.x;  // 256
    // zero pad cols 40..47
    for (int idx = tid; idx < 512; idx += 256) {
        Qs[idx >> 3][40 + (idx & 7)] = __float2half(0.f);
        Ks[idx >> 3][40 + (idx & 7)] = __float2half(0.f);
    }
    for (int idx = tid; idx < 640; idx += 256) {
        int r = idx / 10, c4 = (idx % 10) * 4;
        float4 q = *(const float4*)&Qb[(long)(n0 + r) * 960 + c4];
        float4 k2 = *(const float4*)&Kb[(long)(m0 + r) * 960 + c4];
        *(__half2*)&Qs[r][c4]     = __floats2half2_rn(q.x, q.y);
        *(__half2*)&Qs[r][c4 + 2] = __floats2half2_rn(q.z, q.w);
        *(__half2*)&Ks[r][c4]     = __floats2half2_rn(k2.x, k2.y);
        *(__half2*)&Ks[r][c4 + 2] = __floats2half2_rn(k2.z, k2.w);
    }
    __syncthreads();
    int w = tid >> 5, wr = w >> 1, wc = w & 1;
    wmma::fragment<wmma::accumulator, 16, 16, 16, float> c[2];
    wmma::fill_fragment(c[0], 0.f);
    wmma::fill_fragment(c[1], 0.f);
    #pragma unroll
    for (int kk = 0; kk < 3; kk++) {
        wmma::fragment<wmma::matrix_a, 16, 16, 16, __half, wmma::row_major> a;
        wmma::load_matrix_sync(a, &Qs[wr * 16][kk * 16], 48);
        #pragma unroll
        for (int j = 0; j < 2; j++) {
            wmma::fragment<wmma::matrix_b, 16, 16, 16, __half, wmma::col_major> bf;
            wmma::load_matrix_sync(bf, &Ks[wc * 32 + j * 16][kk * 16], 48);
            wmma::mma_sync(c[j], a, bf, c[j]);
        }
    }
    float* op = g_attn + ((long)b * NHh + h) * Nn * Nn;
    #pragma unroll
    for (int j = 0; j < 2; j++) {
        #pragma unroll
        for (int e = 0; e < c[j].num_elements; e++) c[j].x[e] *= ATT_SCALE;
        wmma::store_matrix_sync(&op[(long)(n0 + wr * 16) * Nn + m0 + wc * 32 + j * 16],
                                c[j], Nn, wmma::mem_row_major);
    }
}

__device__ __forceinline__ void mergeTriple(float& m, float& z, float& s,
                                            float mo, float zo, float so) {
    float nm = fmaxf(m, mo);
    float f1 = __expf(m - nm), f2 = __expf(mo - nm);
    z = z * f1 + zo * f2;
    s = s * f1 + so * f2;
    m = nm;
}

// warp-per-head: r = rawscore + edge*ew + eb; softmax; probs(fp16) out;
// edge_new cross-head; edge update; wsum. Edge row staged in smem once.
__global__ void softmax_ednew(const float* __restrict__ exp_w, const float* __restrict__ exp_b,
                              const float* __restrict__ red_w, const float* __restrict__ red_b) {
    __shared__ float es[Nn];        // edge row
    __shared__ float Ts[NHh][Nn];   // rw*(a+r)
    __shared__ float red3[24];
    int bn = blockIdx.x;
    int b = bn >> 10, n = bn & 1023;
    int tid = threadIdx.x;          // 256 = 8 warps
    int w = tid >> 5, lane = tid & 31;
    const float* Ab = g_attn + (((long)b * NHh + w) * Nn + n) * Nn;
    __half* Pb = g_probs + (((long)b * NHh + w) * Nn + n) * Nn;
    float* ep = g_edge + (long)b * Nn * Nn + (long)n * Nn;
    // stage edge row
    *(float4*)&es[tid * 4] = *(const float4*)&ep[tid * 4];
    __syncthreads();
    float ew = exp_w[w], eb = exp_b[w], rw = red_w[w];

    float4 r[8], e[8];
    #pragma unroll
    for (int k = 0; k < 8; k++) {
        float4 s = *(const float4*)&Ab[lane * 4 + k * 128];
        float4 ev = *(float4*)&es[lane * 4 + k * 128];
        r[k].x = s.x + ev.x * ew + eb; r[k].y = s.y + ev.y * ew + eb;
        r[k].z = s.z + ev.z * ew + eb; r[k].w = s.w + ev.w * ew + eb;
    }
    float M = -INFINITY;
    #pragma unroll
    for (int k = 0; k < 8; k++)
        M = fmaxf(M, fmaxf(fmaxf(r[k].x, r[k].y), fmaxf(r[k].z, r[k].w)));
    #pragma unroll
    for (int o = 16; o > 0; o >>= 1) M = fmaxf(M, __shfl_xor_sync(0xffffffffu, M, o));
    float Z = 0.f;
    #pragma unroll
    for (int k = 0; k < 8; k++) {
        e[k].x = __expf(r[k].x - M); e[k].y = __expf(r[k].y - M);
        e[k].z = __expf(r[k].z - M); e[k].w = __expf(r[k].w - M);
        Z += e[k].x + e[k].y + e[k].z + e[k].w;
    }
    #pragma unroll
    for (int o = 16; o > 0; o >>= 1) Z += __shfl_xor_sync(0xffffffffu, Z, o);
    float inv = 1.f / Z;
    #pragma unroll
    for (int k = 0; k < 8; k++) {
        float ax = e[k].x * inv, ay = e[k].y * inv, az = e[k].z * inv, aw = e[k].w * inv;
        __half2 h0 = __floats2half2_rn(ax, ay);
        __half2 h1 = __floats2half2_rn(az, aw);
        *(__half2*)&Pb[lane * 4 + k * 128]     = h0;
        *(__half2*)&Pb[lane * 4 + k * 128 + 2] = h1;
        float4 t;
        t.x = rw * (ax + r[k].x); t.y = rw * (ay + r[k].y);
        t.z = rw * (az + r[k].z); t.w = rw * (aw + r[k].w);
        *(float4*)&Ts[w][lane * 4 + k * 128] = t;
    }
    __syncthreads();

    // phase 2: cross-head sum at cols tid*4..+3
    float rb = red_b[0];
    float4 en = {rb, rb, rb, rb};
    #pragma unroll
    for (int h = 0; h < NHh; h++) {
        float4 t = *(float4*)&Ts[h][tid * 4];
        en.x += t.x; en.y += t.y; en.z += t.z; en.w += t.w;
    }
    float4 ec = *(float4*)&es[tid * 4];
    ec.x += en.x; ec.y += en.y; ec.z += en.z; ec.w += en.w;
    *(float4*)&ep[tid * 4] = ec;
    float m2 = fmaxf(fmaxf(en.x, en.y), fmaxf(en.z, en.w));
    float f0 = __expf(en.x - m2), f1 = __expf(en.y - m2),
          f2 = __expf(en.z - m2), f3 = __expf(en.w - m2);
    float z2 = f0 + f1 + f2 + f3;
    float s2 = f0 * en.x + f1 * en.y + f2 * en.z + f3 * en.w;
    #pragma unroll
    for (int o = 16; o > 0; o >>= 1)
        mergeTriple(m2, z2, s2,
                    __shfl_xor_sync(0xffffffffu, m2, o),
                    __shfl_xor_sync(0xffffffffu, z2, o),
                    __shfl_xor_sync(0xffffffffu, s2, o));
    if (lane == 0) { red3[w * 3] = m2; red3[w * 3 + 1] = z2; red3[w * 3 + 2] = s2; }
    __syncthreads();
    if (tid < 32) {
        float mm = (lane < 8) ? red3[lane * 3]     : -INFINITY;
        float zz = (lane < 8) ? red3[lane * 3 + 1] : 0.f;
        float ss = (lane < 8) ? red3[lane * 3 + 2] : 0.f;
        #pragma unroll
        for (int o = 4; o > 0; o >>= 1)
            mergeTriple(mm, zz, ss,
                        __shfl_xor_sync(0xffffffffu, mm, o),
                        __shfl_xor_sync(0xffffffffu, zz, o),
                        __shfl_xor_sync(0xffffffffu, ss, o));
        if (lane == 0) g_wsum[bn] = ss / zz;
    }
}

// AV (fp16 WMMA): node_out = P @ V + wsum. A loaded straight from global probs.
// grid (16 n-tiles of 64, Bb*NHh), 128 threads = 4 warps x 16 rows.
__global__ void av_half(void) {
    __shared__ __half Vs[64][48];
    __shared__ float Cs[64][48];
    int bh = blockIdx.y;
    int b = bh >> 3, h = bh & 7;
    int n0 = blockIdx.x * 64;
    int tid = threadIdx.x;  // 128
    int w = tid >> 5;
    const __half* Ap = g_probs + (((long)b * NHh + h) * Nn + n0) * Nn;
    const float* Vb = g_qkv + (long)b * Nn * 960 + 2 * Cc + h * DHh;
    for (int idx = tid; idx < 512; idx += 128) Vs[idx >> 3][40 + (idx & 7)] = __float2half(0.f);
    wmma::fragment<wmma::accumulator, 16, 16, 16, float> c[3];
    #pragma unroll
    for (int j = 0; j < 3; j++) wmma::fill_fragment(c[j], 0.f);
    for (int m0 = 0; m0 < Nn; m0 += 64) {
        __syncthreads();
        for (int idx = tid; idx < 640; idx += 128) {
            int r = idx / 10, c4 = (idx % 10) * 4;
            float4 v = *(const float4*)&Vb[(long)(m0 + r) * 960 + c4];
            *(__half2*)&Vs[r][c4]     = __floats2half2_rn(v.x, v.y);
            *(__half2*)&Vs[r][c4 + 2] = __floats2half2_rn(v.z, v.w);
        }
        __syncthreads();
        #pragma unroll
        for (int kk = 0; kk < 4; kk++) {
            wmma::fragment<wmma::matrix_a, 16, 16, 16, __half, wmma::row_major> a;
            wmma::load_matrix_sync(a, Ap + (long)(w * 16) * Nn + m0 + kk * 16, Nn);
            #pragma unroll
            for (int j = 0; j < 3; j++) {
                wmma::fragment<wmma::matrix_b, 16, 16, 16, __half, wmma::row_major> bf;
                wmma::load_matrix_sync(bf, &Vs[kk * 16][j * 16], 48);
                wmma::mma_sync(c[j], a, bf, c[j]);
            }
        }
    }
    __syncthreads();
    #pragma unroll
    for (int j = 0; j < 3; j++)
        wmma::store_matrix_sync(&Cs[w * 16][j * 16], c[j], 48, wmma::mem_row_major);
    __syncthreads();
    const float* wsp = g_wsum + b * Nn + n0;
    float* op = g_nodeout + ((long)b * Nn + n0) * Cc + h * DHh;
    for (int idx = tid; idx < 640; idx += 128) {
        int r = idx / 10, c4 = (idx % 10) * 4;
        float wv = wsp[r];
        float4 v = *(float4*)&Cs[r][c4];
        v.x += wv; v.y += wv; v.z += wv; v.w += wv;
        *(float4*)&op[(long)r * Cc + c4] = v;
    }
}

static float* sym(const void* s) {
    void* p = nullptr;
    cudaGetSymbolAddress(&p, s);
    return (float*)p;
}

extern "C" void kernel_launch(void* const* d_in, const int* in_sizes, int n_in,
                              void* d_out, int out_size) {
    const float* x        = (const float*)d_in[0];
    const float* da_prior = (const float*)d_in[1];
    const float* qk_w     = (const float*)d_in[2];
    const float* fcp_w    = (const float*)d_in[3];
    const float* fcp_b    = (const float*)d_in[4];
    const float* ln1_g    = (const float*)d_in[5];
    const float* ln1_b    = (const float*)d_in[6];
    const float* gln_g    = (const float*)d_in[7];
    const float* gln_b    = (const float*)d_in[8];
    const float* qkv_w    = (const float*)d_in[9];
    const float* qkv_b    = (const float*)d_in[10];
    const float* proj_w   = (const float*)d_in[11];
    const float* proj_b   = (const float*)d_in[12];
    const float* exp_w    = (const float*)d_in[13];
    const float* exp_b    = (const float*)d_in[14];
    const float* red_w    = (const float*)d_in[15];
    const float* red_b    = (const float*)d_in[16];
    float* out = (float*)d_out;

    float* p_node    = sym(g_node);
    float* p_qk2     = sym(g_qk2);
    float* p_edge    = sym(g_edge);
    float* p_y       = sym(g_y);
    float* p_qkv     = sym(g_qkv);
    float* p_nodeout = sym(g_nodeout);

    transpose_in<<<dim3(32, 10, Bb), dim3(32, 32)>>>(x);
    gemm_tf32<<<dim3(10, 16, 1), 256>>>(p_node, qk_w, nullptr, p_qk2,
                                        Bb * Nn, 2 * Cc, Cc, Cc, Cc, 2 * Cc, 0, 0, 0, 1.f);
    gemm_tf32<<<dim3(16, 8, Bb), 256>>>(p_qk2, p_qk2 + Cc, nullptr, p_edge,
                                        Nn, Nn, Cc, 2 * Cc, 2 * Cc, Nn,
                                        (long)Nn * 2 * Cc, (long)Nn * 2 * Cc, (long)Nn * Nn,
                                        EDGE_SCALE);
    edge_softmax<<<Bb * Nn, 256>>>();
    fcp_kernel<<<Bb, Cc>>>(da_prior, fcp_w, fcp_b);

    for (int l = 0; l < Ll; l++) {
        norm_kernel<<<Bb * Nn, Cc>>>(ln1_g + l * Cc, ln1_b + l * Cc,
                                     gln_g + l * Cc, gln_b + l * Cc);
        gemm_tf32<<<dim3(15, 16, 1), 256>>>(p_y, qkv_w + (long)l * 3 * Cc * Cc,
                                            qkv_b + l * 3 * Cc, p_qkv,
                                            Bb * Nn, 3 * Cc, Cc, Cc, Cc, 3 * Cc, 0, 0, 0, 1.f);
        attn_score_half<<<dim3(16, 16, Bb * NHh), 256>>>();
        softmax_ednew<<<Bb * Nn, 256>>>(exp_w + l * NHh, exp_b + l * NHh,
                                        red_w + l * NHh, red_b + l);
        av_half<<<dim3(16, Bb * NHh), 128>>>();
        gemm_tf32<<<dim3(5, 16, 1), 256>>>(p_nodeout, proj_w + (long)l * Cc * Cc,
                                           proj_b + l * Cc, p_node,
                                           Bb * Nn, Cc, Cc, Cc, Cc, Cc, 0, 0, 0, 1.f);
    }
    transpose_out<<<dim3(32, 10, Bb), dim3(32, 32)>>>(out);
}

// round 8
// speedup vs baseline: 2.1199x; 1.2496x over previous
#include <cuda_runtime.h>
#include <cuda_fp16.h>
#include <mma.h>
#include <math.h>

using namespace nvcuda;

#define Bb 2
#define Cc 320
#define Nn 1024
#define NHh 8
#define DHh 40
#define Ll 2
#define EPS 1e-5f
#define EDGE_SCALE 0.17677669529663687f
#define ATT_SCALE  0.15811388300841897f

__device__ float g_node[Bb * Nn * Cc];
__device__ float g_qk2[Bb * Nn * 2 * Cc];
__device__ float g_edge[Bb * Nn * Nn];
__device__ float g_s[Bb * Cc];
__device__ float g_y[Bb * Nn * Cc];
__device__ float g_qkv[Bb * Nn * 3 * Cc];
__device__ __half g_sattn[Bb * NHh * Nn * Nn];   // raw QK^T*scale (fp16)
__device__ __half g_probs[Bb * NHh * Nn * Nn];   // softmax probs (fp16)
__device__ float g_wsum[Bb * Nn];
__device__ float g_nodeout[Bb * Nn * Cc];

__global__ void transpose_in(const float* __restrict__ x) {
    __shared__ float tile[32][33];
    int b = blockIdx.z;
    int c0 = blockIdx.y * 32, n0 = blockIdx.x * 32;
    int tx = threadIdx.x, ty = threadIdx.y;
    tile[ty][tx] = x[(long)b * Cc * Nn + (long)(c0 + ty) * Nn + n0 + tx];
    __syncthreads();
    g_node[((long)b * Nn + n0 + ty) * Cc + c0 + tx] = tile[tx][ty];
}

__global__ void transpose_out(float* __restrict__ out) {
    __shared__ float tile[32][33];
    int b = blockIdx.z;
    int c0 = blockIdx.y * 32, n0 = blockIdx.x * 32;
    int tx = threadIdx.x, ty = threadIdx.y;
    tile[ty][tx] = g_node[((long)b * Nn + n0 + ty) * Cc + c0 + tx];
    __syncthreads();
    out[(long)b * Cc * Nn + (long)(c0 + ty) * Nn + n0 + tx] = tile[tx][ty];
}

// FP16 WMMA NT GEMM: C = alpha*A@W^T + bias (fp32 accum). Block 128x64, K-tile 32.
__global__ void gemm_half(const float* __restrict__ A, const float* __restrict__ W,
                          const float* __restrict__ bias, float* __restrict__ C,
                          int M, int Ncols, int K, int lda, int ldw, int ldc,
                          long sA, long sW, long sC, float alpha) {
    __shared__ float sbuf[8704];                       // 34816 B
    __half (*As)[40] = (__half(*)[40])sbuf;            // 128x40 half = 10240 B
    __half (*Ws)[40] = (__half(*)[40])(sbuf + 2560);   // 64x40 half = 5120 B
    int z = blockIdx.z;
    A += (long)z * sA; W += (long)z * sW; C += (long)z * sC;
    int bm = blockIdx.y * 128, bn = blockIdx.x * 64;
    int tid = threadIdx.x;
    int w = tid >> 5;
    int wm = w >> 1, wn = w & 1;
    wmma::fragment<wmma::accumulator, 16, 16, 16, float> c[2][2];
    #pragma unroll
    for (int i = 0; i < 2; i++)
        #pragma unroll
        for (int j = 0; j < 2; j++) wmma::fill_fragment(c[i][j], 0.f);
    for (int k0 = 0; k0 < K; k0 += 32) {
        #pragma unroll
        for (int i = 0; i < 4; i++) {   // A: 128x32 = 1024 float4
            int idx = tid + i * 256;
            int r = idx >> 3, c4 = (idx & 7) * 4;
            float4 v = *(const float4*)&A[(long)(bm + r) * lda + k0 + c4];
            *(__half2*)&As[r][c4]     = __floats2half2_rn(v.x, v.y);
            *(__half2*)&As[r][c4 + 2] = __floats2half2_rn(v.z, v.w);
        }
        #pragma unroll
        for (int i = 0; i < 2; i++) {   // W: 64x32 = 512 float4
            int idx = tid + i * 256;
            int r = idx >> 3, c4 = (idx & 7) * 4;
            float4 v = *(const float4*)&W[(long)(bn + r) * ldw + k0 + c4];
            *(__half2*)&Ws[r][c4]     = __floats2half2_rn(v.x, v.y);
            *(__half2*)&Ws[r][c4 + 2] = __floats2half2_rn(v.z, v.w);
        }
        __syncthreads();
        #pragma unroll
        for (int kk = 0; kk < 2; kk++) {
            wmma::fragment<wmma::matrix_a, 16, 16, 16, __half, wmma::row_major> a[2];
            wmma::fragment<wmma::matrix_b, 16, 16, 16, __half, wmma::col_major> bf[2];
            #pragma unroll
            for (int i = 0; i < 2; i++)
                wmma::load_matrix_sync(a[i], &As[wm * 32 + i * 16][kk * 16], 40);
            #pragma unroll
            for (int j = 0; j < 2; j++)
                wmma::load_matrix_sync(bf[j], &Ws[wn * 32 + j * 16][kk * 16], 40);
            #pragma unroll
            for (int i = 0; i < 2; i++)
                #pragma unroll
                for (int j = 0; j < 2; j++) wmma::mma_sync(c[i][j], a[i], bf[j], c[i][j]);
        }
        __syncthreads();
    }
    #pragma unroll
    for (int i = 0; i < 2; i++)
        #pragma unroll
        for (int j = 0; j < 2; j++) {
            #pragma unroll
            for (int e = 0; e < c[i][j].num_elements; e++) c[i][j].x[e] *= alpha;
            wmma::store_matrix_sync(&sbuf[(wm * 32 + i * 16) * 68 + wn * 32 + j * 16],
                                    c[i][j], 68, wmma::mem_row_major);
        }
    __syncthreads();
    #pragma unroll
    for (int i = 0; i < 8; i++) {
        int idx = tid + i * 256;
        int r = idx >> 4, c4 = (idx & 15) * 4;
        float4 v = *(float4*)&sbuf[r * 68 + c4];
        if (bias) {
            float4 bb = *(const float4*)&bias[bn + c4];
            v.x += bb.x; v.y += bb.y; v.z += bb.z; v.w += bb.w;
        }
        *(float4*)&C[(long)(bm + r) * ldc + bn + c4] = v;
    }
}

// warp-per-row edge softmax (in-place), 8 rows/block, shuffle-only.
__global__ void edge_softmax(void) {
    int row = blockIdx.x * 8 + (threadIdx.x >> 5);
    int lane = threadIdx.x & 31;
    float* p = g_edge + (long)row * Nn;
    float4 r[8];
    float mx = -INFINITY;
    #pragma unroll
    for (int k = 0; k < 8; k++) {
        r[k] = *(float4*)&p[lane * 4 + k * 128];
        mx = fmaxf(mx, fmaxf(fmaxf(r[k].x, r[k].y), fmaxf(r[k].z, r[k].w)));
    }
    #pragma unroll
    for (int o = 16; o > 0; o >>= 1) mx = fmaxf(mx, __shfl_xor_sync(0xffffffffu, mx, o));
    float Z = 0.f;
    #pragma unroll
    for (int k = 0; k < 8; k++) {
        r[k].x = __expf(r[k].x - mx); r[k].y = __expf(r[k].y - mx);
        r[k].z = __expf(r[k].z - mx); r[k].w = __expf(r[k].w - mx);
        Z += r[k].x + r[k].y + r[k].z + r[k].w;
    }
    #pragma unroll
    for (int o = 16; o > 0; o >>= 1) Z += __shfl_xor_sync(0xffffffffu, Z, o);
    float inv = 1.f / Z;
    #pragma unroll
    for (int k = 0; k < 8; k++) {
        r[k].x *= inv; r[k].y *= inv; r[k].z *= inv; r[k].w *= inv;
        *(float4*)&p[lane * 4 + k * 128] = r[k];
    }
}

__global__ void fcp_kernel(const float* __restrict__ da, const float* __restrict__ fw,
                           const float* __restrict__ fb) {
    __shared__ float t[64];
    int b = blockIdx.x;
    int tid = threadIdx.x;
    if (tid < 64) {
        float s = 0.f;
        #pragma unroll
        for (int a = 0; a < 16; a++) s += da[(long)b * 16 * 64 + a * 64 + tid];
        t[tid] = s;
    }
    __syncthreads();
    float s = 16.f * fb[tid];
    #pragma unroll
    for (int e = 0; e < 64; e++) s += t[e] * fw[tid * 64 + e];
    g_s[b * Cc + tid] = s;
}

// warp-per-row LN1 -> gate -> LN2, 8 rows/block, shuffle-only.
__global__ void norm_kernel(const float* __restrict__ g1, const float* __restrict__ b1,
                            const float* __restrict__ g2, const float* __restrict__ b2) {
    int bn = blockIdx.x * 8 + (threadIdx.x >> 5);
    int b = bn >> 10, n = bn & 1023;
    int lane = threadIdx.x & 31;
    const float* xp = g_node + (long)bn * Cc;
    float x[10];
    float s = 0.f;
    #pragma unroll
    for (int j = 0; j < 10; j++) { x[j] = xp[lane + j * 32]; s += x[j]; }
    #pragma unroll
    for (int o = 16; o > 0; o >>= 1) s += __shfl_xor_sync(0xffffffffu, s, o);
    float mean = s * (1.f / Cc);
    float v = 0.f;
    #pragma unroll
    for (int j = 0; j < 10; j++) { x[j] -= mean; v += x[j] * x[j]; }
    #pragma unroll
    for (int o = 16; o > 0; o >>= 1) v += __shfl_xor_sync(0xffffffffu, v, o);
    float rstd = rsqrtf(v * (1.f / Cc) + EPS);
    float diag = g_edge[(long)b * Nn * Nn + (long)n * Nn + n];
    const float* gsp = g_s + b * Cc;
    float y[10];
    float s2 = 0.f;
    #pragma unroll
    for (int j = 0; j < 10; j++) {
        int c = lane + j * 32;
        float nt = x[j] * rstd * g1[c] + b1[c];
        y[j] = diag * nt * gsp[c] + nt;
        s2 += y[j];
    }
    #pragma unroll
    for (int o = 16; o > 0; o >>= 1) s2 += __shfl_xor_sync(0xffffffffu, s2, o);
    float mean2 = s2 * (1.f / Cc);
    float v2 = 0.f;
    #pragma unroll
    for (int j = 0; j < 10; j++) { y[j] -= mean2; v2 += y[j] * y[j]; }
    #pragma unroll
    for (int o = 16; o > 0; o >>= 1) v2 += __shfl_xor_sync(0xffffffffu, v2, o);
    float rstd2 = rsqrtf(v2 * (1.f / Cc) + EPS);
    float* yp = g_y + (long)bn * Cc;
    #pragma unroll
    for (int j = 0; j < 10; j++) {
        int c = lane + j * 32;
        yp[c] = y[j] * rstd2 * g2[c] + b2[c];
    }
}

// attn scores (fp16 WMMA): RAW QK^T*ATT_SCALE -> g_sattn (fp16, via smem epilogue)
__global__ void attn_score_half(void) {
    __shared__ __half Qs[64][48];
    __shared__ __half Ks[64][48];
    __shared__ float Cs[64][68];
    int bh = blockIdx.z;
    int b = bh >> 3, h = bh & 7;
    int n0 = blockIdx.y * 64, m0 = blockIdx.x * 64;
    const float* Qb = g_qkv + (long)b * Nn * 960 + h * DHh;
    const float* Kb = Qb + Cc;
    int tid = threadIdx.x;  // 256
    for (int idx = tid; idx < 512; idx += 256) {
        Qs[idx >> 3][40 + (idx & 7)] = __float2half(0.f);
        Ks[idx >> 3][40 + (idx & 7)] = __float2half(0.f);
    }
    for (int idx = tid; idx < 640; idx += 256) {
        int r = idx / 10, c4 = (idx % 10) * 4;
        float4 q = *(const float4*)&Qb[(long)(n0 + r) * 960 + c4];
        float4 k2 = *(const float4*)&Kb[(long)(m0 + r) * 960 + c4];
        *(__half2*)&Qs[r][c4]     = __floats2half2_rn(q.x, q.y);
        *(__half2*)&Qs[r][c4 + 2] = __floats2half2_rn(q.z, q.w);
        *(__half2*)&Ks[r][c4]     = __floats2half2_rn(k2.x, k2.y);
        *(__half2*)&Ks[r][c4 + 2] = __floats2half2_rn(k2.z, k2.w);
    }
    __syncthreads();
    int w = tid >> 5, wr = w >> 1, wc = w & 1;
    wmma::fragment<wmma::accumulator, 16, 16, 16, float> c[2];
    wmma::fill_fragment(c[0], 0.f);
    wmma::fill_fragment(c[1], 0.f);
    #pragma unroll
    for (int kk = 0; kk < 3; kk++) {
        wmma::fragment<wmma::matrix_a, 16, 16, 16, __half, wmma::row_major> a;
        wmma::load_matrix_sync(a, &Qs[wr * 16][kk * 16], 48);
        #pragma unroll
        for (int j = 0; j < 2; j++) {
            wmma::fragment<wmma::matrix_b, 16, 16, 16, __half, wmma::col_major> bf;
            wmma::load_matrix_sync(bf, &Ks[wc * 32 + j * 16][kk * 16], 48);
            wmma::mma_sync(c[j], a, bf, c[j]);
        }
    }
    #pragma unroll
    for (int j = 0; j < 2; j++) {
        #pragma unroll
        for (int e = 0; e < c[j].num_elements; e++) c[j].x[e] *= ATT_SCALE;
        wmma::store_matrix_sync(&Cs[wr * 16][wc * 32 + j * 16], c[j], 68, wmma::mem_row_major);
    }
    __syncthreads();
    __half* op = g_sattn + ((long)b * NHh + h) * Nn * Nn;
    #pragma unroll
    for (int i = 0; i < 4; i++) {
        int idx = tid + i * 256;
        int r = idx >> 4, c4 = (idx & 15) * 4;
        float4 s = *(float4*)&Cs[r][c4];
        *(__half2*)&op[(long)(n0 + r) * Nn + m0 + c4]     = __floats2half2_rn(s.x, s.y);
        *(__half2*)&op[(long)(n0 + r) * Nn + m0 + c4 + 2] = __floats2half2_rn(s.z, s.w);
    }
}

__device__ __forceinline__ void mergeTriple(float& m, float& z, float& s,
                                            float mo, float zo, float so) {
    float nm = fmaxf(m, mo);
    float f1 = __expf(m - nm), f2 = __expf(mo - nm);
    z = z * f1 + zo * f2;
    s = s * f1 + so * f2;
    m = nm;
}

// warp-per-head: r = rawscore(fp16) + edge*ew + eb; softmax; probs(fp16);
// edge_new cross-head; edge update; wsum.
__global__ void softmax_ednew(const float* __restrict__ exp_w, const float* __restrict__ exp_b,
                              const float* __restrict__ red_w, const float* __restrict__ red_b) {
    __shared__ float es[Nn];
    __shared__ float Ts[NHh][Nn];
    __shared__ float red3[24];
    int bn = blockIdx.x;
    int b = bn >> 10, n = bn & 1023;
    int tid = threadIdx.x;  // 256 = 8 warps
    int w = tid >> 5, lane = tid & 31;
    const __half* Ab = g_sattn + (((long)b * NHh + w) * Nn + n) * Nn;
    __half* Pb = g_probs + (((long)b * NHh + w) * Nn + n) * Nn;
    float* ep = g_edge + (long)b * Nn * Nn + (long)n * Nn;
    *(float4*)&es[tid * 4] = *(const float4*)&ep[tid * 4];
    __syncthreads();
    float ew = exp_w[w], eb = exp_b[w], rw = red_w[w];

    float4 r[8], e[8];
    #pragma unroll
    for (int k = 0; k < 8; k++) {
        __half2 h0 = *(const __half2*)&Ab[lane * 4 + k * 128];
        __half2 h1 = *(const __half2*)&Ab[lane * 4 + k * 128 + 2];
        float2 f0 = __half22float2(h0), f1 = __half22float2(h1);
        float4 ev = *(float4*)&es[lane * 4 + k * 128];
        r[k].x = f0.x + ev.x * ew + eb; r[k].y = f0.y + ev.y * ew + eb;
        r[k].z = f1.x + ev.z * ew + eb; r[k].w = f1.y + ev.w * ew + eb;
    }
    float M = -INFINITY;
    #pragma unroll
    for (int k = 0; k < 8; k++)
        M = fmaxf(M, fmaxf(fmaxf(r[k].x, r[k].y), fmaxf(r[k].z, r[k].w)));
    #pragma unroll
    for (int o = 16; o > 0; o >>= 1) M = fmaxf(M, __shfl_xor_sync(0xffffffffu, M, o));
    float Z = 0.f;
    #pragma unroll
    for (int k = 0; k < 8; k++) {
        e[k].x = __expf(r[k].x - M); e[k].y = __expf(r[k].y - M);
        e[k].z = __expf(r[k].z - M); e[k].w = __expf(r[k].w - M);
        Z += e[k].x + e[k].y + e[k].z + e[k].w;
    }
    #pragma unroll
    for (int o = 16; o > 0; o >>= 1) Z += __shfl_xor_sync(0xffffffffu, Z, o);
    float inv = 1.f / Z;
    #pragma unroll
    for (int k = 0; k < 8; k++) {
        float ax = e[k].x * inv, ay = e[k].y * inv, az = e[k].z * inv, aw = e[k].w * inv;
        *(__half2*)&Pb[lane * 4 + k * 128]     = __floats2half2_rn(ax, ay);
        *(__half2*)&Pb[lane * 4 + k * 128 + 2] = __floats2half2_rn(az, aw);
        float4 t;
        t.x = rw * (ax + r[k].x); t.y = rw * (ay + r[k].y);
        t.z = rw * (az + r[k].z); t.w = rw * (aw + r[k].w);
        *(float4*)&Ts[w][lane * 4 + k * 128] = t;
    }
    __syncthreads();

    float rb = red_b[0];
    float4 en = {rb, rb, rb, rb};
    #pragma unroll
    for (int h = 0; h < NHh; h++) {
        float4 t = *(float4*)&Ts[h][tid * 4];
        en.x += t.x; en.y += t.y; en.z += t.z; en.w += t.w;
    }
    float4 ec = *(float4*)&es[tid * 4];
    ec.x += en.x; ec.y += en.y; ec.z += en.z; ec.w += en.w;
    *(float4*)&ep[tid * 4] = ec;
    float m2 = fmaxf(fmaxf(en.x, en.y), fmaxf(en.z, en.w));
    float f0 = __expf(en.x - m2), f1 = __expf(en.y - m2),
          f2 = __expf(en.z - m2), f3 = __expf(en.w - m2);
    float z2 = f0 + f1 + f2 + f3;
    float s2 = f0 * en.x + f1 * en.y + f2 * en.z + f3 * en.w;
    #pragma unroll
    for (int o = 16; o > 0; o >>= 1)
        mergeTriple(m2, z2, s2,
                    __shfl_xor_sync(0xffffffffu, m2, o),
                    __shfl_xor_sync(0xffffffffu, z2, o),
                    __shfl_xor_sync(0xffffffffu, s2, o));
    if (lane == 0) { red3[w * 3] = m2; red3[w * 3 + 1] = z2; red3[w * 3 + 2] = s2; }
    __syncthreads();
    if (tid < 32) {
        float mm = (lane < 8) ? red3[lane * 3]     : -INFINITY;
        float zz = (lane < 8) ? red3[lane * 3 + 1] : 0.f;
        float ss = (lane < 8) ? red3[lane * 3 + 2] : 0.f;
        #pragma unroll
        for (int o = 4; o > 0; o >>= 1)
            mergeTriple(mm, zz, ss,
                        __shfl_xor_sync(0xffffffffu, mm, o),
                        __shfl_xor_sync(0xffffffffu, zz, o),
                        __shfl_xor_sync(0xffffffffu, ss, o));
        if (lane == 0) g_wsum[bn] = ss / zz;
    }
}

// AV (fp16 WMMA): node_out = P @ V + wsum. A loaded straight from global probs.
__global__ void av_half(void) {
    __shared__ __half Vs[64][48];
    __shared__ float Cs[64][48];
    int bh = blockIdx.y;
    int b = bh >> 3, h = bh & 7;
    int n0 = blockIdx.x * 64;
    int tid = threadIdx.x;  // 128
    int w = tid >> 5;
    const __half* Ap = g_probs + (((long)b * NHh + h) * Nn + n0) * Nn;
    const float* Vb = g_qkv + (long)b * Nn * 960 + 2 * Cc + h * DHh;
    for (int idx = tid; idx < 512; idx += 128) Vs[idx >> 3][40 + (idx & 7)] = __float2half(0.f);
    wmma::fragment<wmma::accumulator, 16, 16, 16, float> c[3];
    #pragma unroll
    for (int j = 0; j < 3; j++) wmma::fill_fragment(c[j], 0.f);
    for (int m0 = 0; m0 < Nn; m0 += 64) {
        __syncthreads();
        for (int idx = tid; idx < 640; idx += 128) {
            int r = idx / 10, c4 = (idx % 10) * 4;
            float4 v = *(const float4*)&Vb[(long)(m0 + r) * 960 + c4];
            *(__half2*)&Vs[r][c4]     = __floats2half2_rn(v.x, v.y);
            *(__half2*)&Vs[r][c4 + 2] = __floats2half2_rn(v.z, v.w);
        }
        __syncthreads();
        #pragma unroll
        for (int kk = 0; kk < 4; kk++) {
            wmma::fragment<wmma::matrix_a, 16, 16, 16, __half, wmma::row_major> a;
            wmma::load_matrix_sync(a, Ap + (long)(w * 16) * Nn + m0 + kk * 16, Nn);
            #pragma unroll
            for (int j = 0; j < 3; j++) {
                wmma::fragment<wmma::matrix_b, 16, 16, 16, __half, wmma::row_major> bf;
                wmma::load_matrix_sync(bf, &Vs[kk * 16][j * 16], 48);
                wmma::mma_sync(c[j], a, bf, c[j]);
            }
        }
    }
    __syncthreads();
    #pragma unroll
    for (int j = 0; j < 3; j++)
        wmma::store_matrix_sync(&Cs[w * 16][j * 16], c[j], 48, wmma::mem_row_major);
    __syncthreads();
    const float* wsp = g_wsum + b * Nn + n0;
    float* op = g_nodeout + ((long)b * Nn + n0) * Cc + h * DHh;
    for (int idx = tid; idx < 640; idx += 128) {
        int r = idx / 10, c4 = (idx % 10) * 4;
        float wv = wsp[r];
        float4 v = *(float4*)&Cs[r][c4];
        v.x += wv; v.y += wv; v.z += wv; v.w += wv;
        *(float4*)&op[(long)r * Cc + c4] = v;
    }
}

static float* sym(const void* s) {
    void* p = nullptr;
    cudaGetSymbolAddress(&p, s);
    return (float*)p;
}

extern "C" void kernel_launch(void* const* d_in, const int* in_sizes, int n_in,
                              void* d_out, int out_size) {
    const float* x        = (const float*)d_in[0];
    const float* da_prior = (const float*)d_in[1];
    const float* qk_w     = (const float*)d_in[2];
    const float* fcp_w    = (const float*)d_in[3];
    const float* fcp_b    = (const float*)d_in[4];
    const float* ln1_g    = (const float*)d_in[5];
    const float* ln1_b    = (const float*)d_in[6];
    const float* gln_g    = (const float*)d_in[7];
    const float* gln_b    = (const float*)d_in[8];
    const float* qkv_w    = (const float*)d_in[9];
    const float* qkv_b    = (const float*)d_in[10];
    const float* proj_w   = (const float*)d_in[11];
    const float* proj_b   = (const float*)d_in[12];
    const float* exp_w    = (const float*)d_in[13];
    const float* exp_b    = (const float*)d_in[14];
    const float* red_w    = (const float*)d_in[15];
    const float* red_b    = (const float*)d_in[16];
    float* out = (float*)d_out;

    float* p_node    = sym(g_node);
    float* p_qk2     = sym(g_qk2);
    float* p_edge    = sym(g_edge);
    float* p_y       = sym(g_y);
    float* p_qkv     = sym(g_qkv);
    float* p_nodeout = sym(g_nodeout);

    transpose_in<<<dim3(32, 10, Bb), dim3(32, 32)>>>(x);
    gemm_half<<<dim3(10, 16, 1), 256>>>(p_node, qk_w, nullptr, p_qk2,
                                        Bb * Nn, 2 * Cc, Cc, Cc, Cc, 2 * Cc, 0, 0, 0, 1.f);
    gemm_half<<<dim3(16, 8, Bb), 256>>>(p_qk2, p_qk2 + Cc, nullptr, p_edge,
                                        Nn, Nn, Cc, 2 * Cc, 2 * Cc, Nn,
                                        (long)Nn * 2 * Cc, (long)Nn * 2 * Cc, (long)Nn * Nn,
                                        EDGE_SCALE);
    edge_softmax<<<Bb * Nn / 8, 256>>>();
    fcp_kernel<<<Bb, Cc>>>(da_prior, fcp_w, fcp_b);

    for (int l = 0; l < Ll; l++) {
        norm_kernel<<<Bb * Nn / 8, 256>>>(ln1_g + l * Cc, ln1_b + l * Cc,
                                          gln_g + l * Cc, gln_b + l * Cc);
        gemm_half<<<dim3(15, 16, 1), 256>>>(p_y, qkv_w + (long)l * 3 * Cc * Cc,
                                            qkv_b + l * 3 * Cc, p_qkv,
                                            Bb * Nn, 3 * Cc, Cc, Cc, Cc, 3 * Cc, 0, 0, 0, 1.f);
        attn_score_half<<<dim3(16, 16, Bb * NHh), 256>>>();
        softmax_ednew<<<Bb * Nn, 256>>>(exp_w + l * NHh, exp_b + l * NHh,
                                        red_w + l * NHh, red_b + l);
        av_half<<<dim3(16, Bb * NHh), 128>>>();
        gemm_half<<<dim3(5, 16, 1), 256>>>(p_nodeout, proj_w + (long)l * Cc * Cc,
                                           proj_b + l * Cc, p_node,
                                           Bb * Nn, Cc, Cc, Cc, Cc, Cc, 0, 0, 0, 1.f);
    }
    transpose_out<<<dim3(32, 10, Bb), dim3(32, 32)>>>(out);
}

// round 9
// speedup vs baseline: 2.7719x; 1.3076x over previous
#include <cuda_runtime.h>
#include <cuda_fp16.h>
#include <mma.h>
#include <math.h>

using namespace nvcuda;

#define Bb 2
#define Cc 320
#define Nn 1024
#define NHh 8
#define DHh 40
#define Ll 2
#define EPS 1e-5f
#define EDGE_SCALE 0.17677669529663687f
#define ATT_SCALE  0.15811388300841897f

__device__ float g_node[Bb * Nn * Cc];
__device__ float g_qk2[Bb * Nn * 2 * Cc];
__device__ float g_edge[Bb * Nn * Nn];
__device__ float g_s[Bb * Cc];
__device__ float g_y[Bb * Nn * Cc];
__device__ float g_qkv[Bb * Nn * 3 * Cc];
__device__ __half g_sattn[Bb * NHh * Nn * Nn];   // raw scores, then probs (in-place)
__device__ float g_wsum[Bb * Nn];
__device__ float g_nodeout[Bb * Nn * Cc];

__global__ void transpose_in(const float* __restrict__ x) {
    __shared__ float tile[32][33];
    int b = blockIdx.z;
    int c0 = blockIdx.y * 32, n0 = blockIdx.x * 32;
    int tx = threadIdx.x, ty = threadIdx.y;
    tile[ty][tx] = x[(long)b * Cc * Nn + (long)(c0 + ty) * Nn + n0 + tx];
    __syncthreads();
    g_node[((long)b * Nn + n0 + ty) * Cc + c0 + tx] = tile[tx][ty];
}

__global__ void transpose_out(float* __restrict__ out) {
    __shared__ float tile[32][33];
    int b = blockIdx.z;
    int c0 = blockIdx.y * 32, n0 = blockIdx.x * 32;
    int tx = threadIdx.x, ty = threadIdx.y;
    tile[ty][tx] = g_node[((long)b * Nn + n0 + ty) * Cc + c0 + tx];
    __syncthreads();
    out[(long)b * Cc * Nn + (long)(c0 + ty) * Nn + n0 + tx] = tile[tx][ty];
}

// FP16 WMMA NT GEMM: C = alpha*A@W^T + bias (fp32 accum). Block 128x64, K-tile 64.
__global__ void gemm_half(const float* __restrict__ A, const float* __restrict__ W,
                          const float* __restrict__ bias, float* __restrict__ C,
                          int M, int Ncols, int K, int lda, int ldw, int ldc,
                          long sA, long sW, long sC, float alpha) {
    __shared__ char gsm[34816];                      // union: As|Ws then Cs
    __half (*As)[72] = (__half(*)[72])gsm;           // 128x72 half = 18432 B
    __half (*Ws)[72] = (__half(*)[72])(gsm + 18432); // 64x72 half = 9216 B
    float* sbuf = (float*)gsm;                       // epilogue 128x68 fp32
    int z = blockIdx.z;
    A += (long)z * sA; W += (long)z * sW; C += (long)z * sC;
    int bm = blockIdx.y * 128, bn = blockIdx.x * 64;
    int tid = threadIdx.x;
    int w = tid >> 5;
    int wm = w >> 1, wn = w & 1;
    wmma::fragment<wmma::accumulator, 16, 16, 16, float> c[2][2];
    #pragma unroll
    for (int i = 0; i < 2; i++)
        #pragma unroll
        for (int j = 0; j < 2; j++) wmma::fill_fragment(c[i][j], 0.f);
    for (int k0 = 0; k0 < K; k0 += 64) {
        #pragma unroll
        for (int i = 0; i < 8; i++) {   // A: 128x64 = 2048 float4
            int idx = tid + i * 256;
            int r = idx >> 4, c4 = (idx & 15) * 4;
            float4 v = *(const float4*)&A[(long)(bm + r) * lda + k0 + c4];
            *(__half2*)&As[r][c4]     = __floats2half2_rn(v.x, v.y);
            *(__half2*)&As[r][c4 + 2] = __floats2half2_rn(v.z, v.w);
        }
        #pragma unroll
        for (int i = 0; i < 4; i++) {   // W: 64x64 = 1024 float4
            int idx = tid + i * 256;
            int r = idx >> 4, c4 = (idx & 15) * 4;
            float4 v = *(const float4*)&W[(long)(bn + r) * ldw + k0 + c4];
            *(__half2*)&Ws[r][c4]     = __floats2half2_rn(v.x, v.y);
            *(__half2*)&Ws[r][c4 + 2] = __floats2half2_rn(v.z, v.w);
        }
        __syncthreads();
        #pragma unroll
        for (int kk = 0; kk < 4; kk++) {
            wmma::fragment<wmma::matrix_a, 16, 16, 16, __half, wmma::row_major> a[2];
            wmma::fragment<wmma::matrix_b, 16, 16, 16, __half, wmma::col_major> bf[2];
            #pragma unroll
            for (int i = 0; i < 2; i++)
                wmma::load_matrix_sync(a[i], &As[wm * 32 + i * 16][kk * 16], 72);
            #pragma unroll
            for (int j = 0; j < 2; j++)
                wmma::load_matrix_sync(bf[j], &Ws[wn * 32 + j * 16][kk * 16], 72);
            #pragma unroll
            for (int i = 0; i < 2; i++)
                #pragma unroll
                for (int j = 0; j < 2; j++) wmma::mma_sync(c[i][j], a[i], bf[j], c[i][j]);
        }
        __syncthreads();
    }
    #pragma unroll
    for (int i = 0; i < 2; i++)
        #pragma unroll
        for (int j = 0; j < 2; j++) {
            #pragma unroll
            for (int e = 0; e < c[i][j].num_elements; e++) c[i][j].x[e] *= alpha;
            wmma::store_matrix_sync(&sbuf[(wm * 32 + i * 16) * 68 + wn * 32 + j * 16],
                                    c[i][j], 68, wmma::mem_row_major);
        }
    __syncthreads();
    #pragma unroll
    for (int i = 0; i < 8; i++) {
        int idx = tid + i * 256;
        int r = idx >> 4, c4 = (idx & 15) * 4;
        float4 v = *(float4*)&sbuf[r * 68 + c4];
        if (bias) {
            float4 bb = *(const float4*)&bias[bn + c4];
            v.x += bb.x; v.y += bb.y; v.z += bb.z; v.w += bb.w;
        }
        *(float4*)&C[(long)(bm + r) * ldc + bn + c4] = v;
    }
}

// warp-per-row edge softmax (in-place), 8 rows/block, shuffle-only.
__global__ void edge_softmax(void) {
    int row = blockIdx.x * 8 + (threadIdx.x >> 5);
    int lane = threadIdx.x & 31;
    float* p = g_edge + (long)row * Nn;
    float4 r[8];
    float mx = -INFINITY;
    #pragma unroll
    for (int k = 0; k < 8; k++) {
        r[k] = *(float4*)&p[lane * 4 + k * 128];
        mx = fmaxf(mx, fmaxf(fmaxf(r[k].x, r[k].y), fmaxf(r[k].z, r[k].w)));
    }
    #pragma unroll
    for (int o = 16; o > 0; o >>= 1) mx = fmaxf(mx, __shfl_xor_sync(0xffffffffu, mx, o));
    float Z = 0.f;
    #pragma unroll
    for (int k = 0; k < 8; k++) {
        r[k].x = __expf(r[k].x - mx); r[k].y = __expf(r[k].y - mx);
        r[k].z = __expf(r[k].z - mx); r[k].w = __expf(r[k].w - mx);
        Z += r[k].x + r[k].y + r[k].z + r[k].w;
    }
    #pragma unroll
    for (int o = 16; o > 0; o >>= 1) Z += __shfl_xor_sync(0xffffffffu, Z, o);
    float inv = 1.f / Z;
    #pragma unroll
    for (int k = 0; k < 8; k++) {
        r[k].x *= inv; r[k].y *= inv; r[k].z *= inv; r[k].w *= inv;
        *(float4*)&p[lane * 4 + k * 128] = r[k];
    }
}

__global__ void fcp_kernel(const float* __restrict__ da, const float* __restrict__ fw,
                           const float* __restrict__ fb) {
    __shared__ float t[64];
    int b = blockIdx.x;
    int tid = threadIdx.x;
    if (tid < 64) {
        float s = 0.f;
        #pragma unroll
        for (int a = 0; a < 16; a++) s += da[(long)b * 16 * 64 + a * 64 + tid];
        t[tid] = s;
    }
    __syncthreads();
    float s = 16.f * fb[tid];
    #pragma unroll
    for (int e = 0; e < 64; e++) s += t[e] * fw[tid * 64 + e];
    g_s[b * Cc + tid] = s;
}

// warp-per-row LN1 -> gate -> LN2, 8 rows/block, shuffle-only.
__global__ void norm_kernel(const float* __restrict__ g1, const float* __restrict__ b1,
                            const float* __restrict__ g2, const float* __restrict__ b2) {
    int bn = blockIdx.x * 8 + (threadIdx.x >> 5);
    int b = bn >> 10, n = bn & 1023;
    int lane = threadIdx.x & 31;
    const float* xp = g_node + (long)bn * Cc;
    float x[10];
    float s = 0.f;
    #pragma unroll
    for (int j = 0; j < 10; j++) { x[j] = xp[lane + j * 32]; s += x[j]; }
    #pragma unroll
    for (int o = 16; o > 0; o >>= 1) s += __shfl_xor_sync(0xffffffffu, s, o);
    float mean = s * (1.f / Cc);
    float v = 0.f;
    #pragma unroll
    for (int j = 0; j < 10; j++) { x[j] -= mean; v += x[j] * x[j]; }
    #pragma unroll
    for (int o = 16; o > 0; o >>= 1) v += __shfl_xor_sync(0xffffffffu, v, o);
    float rstd = rsqrtf(v * (1.f / Cc) + EPS);
    float diag = g_edge[(long)b * Nn * Nn + (long)n * Nn + n];
    const float* gsp = g_s + b * Cc;
    float y[10];
    float s2 = 0.f;
    #pragma unroll
    for (int j = 0; j < 10; j++) {
        int c = lane + j * 32;
        float nt = x[j] * rstd * g1[c] + b1[c];
        y[j] = diag * nt * gsp[c] + nt;
        s2 += y[j];
    }
    #pragma unroll
    for (int o = 16; o > 0; o >>= 1) s2 += __shfl_xor_sync(0xffffffffu, s2, o);
    float mean2 = s2 * (1.f / Cc);
    float v2 = 0.f;
    #pragma unroll
    for (int j = 0; j < 10; j++) { y[j] -= mean2; v2 += y[j] * y[j]; }
    #pragma unroll
    for (int o = 16; o > 0; o >>= 1) v2 += __shfl_xor_sync(0xffffffffu, v2, o);
    float rstd2 = rsqrtf(v2 * (1.f / Cc) + EPS);
    float* yp = g_y + (long)bn * Cc;
    #pragma unroll
    for (int j = 0; j < 10; j++) {
        int c = lane + j * 32;
        yp[c] = y[j] * rstd2 * g2[c] + b2[c];
    }
}

// attn scores (fp16 WMMA): RAW QK^T*ATT_SCALE -> g_sattn. 128x128 tiles.
// 256 threads = 8 warps (4 row-groups x 2 col-groups); warp tile 32x64.
__global__ void attn_score_half(void) {
    __shared__ char smraw[34816];
    __half (*Qs)[48] = (__half(*)[48])smraw;             // 128x48 = 12288 B
    __half (*Ks)[48] = (__half(*)[48])(smraw + 12288);   // 128x48 = 12288 B
    float (*Cs)[68] = (float(*)[68])smraw;               // epilogue alias
    int bh = blockIdx.z;
    int b = bh >> 3, h = bh & 7;
    int n0 = blockIdx.y * 128, m0 = blockIdx.x * 128;
    const float* Qb = g_qkv + (long)b * Nn * 960 + h * DHh;
    const float* Kb = Qb + Cc;
    int tid = threadIdx.x;  // 256
    // zero pad cols 40..47 of both tiles
    for (int idx = tid; idx < 1024; idx += 256) {
        Qs[idx >> 3][40 + (idx & 7)] = __float2half(0.f);
        Ks[idx >> 3][40 + (idx & 7)] = __float2half(0.f);
    }
    for (int idx = tid; idx < 1280; idx += 256) {  // 128 rows x 10 float4
        int r = idx / 10, c4 = (idx % 10) * 4;
        float4 q = *(const float4*)&Qb[(long)(n0 + r) * 960 + c4];
        float4 k2 = *(const float4*)&Kb[(long)(m0 + r) * 960 + c4];
        *(__half2*)&Qs[r][c4]     = __floats2half2_rn(q.x, q.y);
        *(__half2*)&Qs[r][c4 + 2] = __floats2half2_rn(q.z, q.w);
        *(__half2*)&Ks[r][c4]     = __floats2half2_rn(k2.x, k2.y);
        *(__half2*)&Ks[r][c4 + 2] = __floats2half2_rn(k2.z, k2.w);
    }
    __syncthreads();
    int w = tid >> 5, wr = w >> 1, wc = w & 1;
    wmma::fragment<wmma::accumulator, 16, 16, 16, float> c[2][4];
    #pragma unroll
    for (int i = 0; i < 2; i++)
        #pragma unroll
        for (int j = 0; j < 4; j++) wmma::fill_fragment(c[i][j], 0.f);
    #pragma unroll
    for (int kk = 0; kk < 3; kk++) {
        wmma::fragment<wmma::matrix_a, 16, 16, 16, __half, wmma::row_major> a[2];
        wmma::fragment<wmma::matrix_b, 16, 16, 16, __half, wmma::col_major> bf[4];
        #pragma unroll
        for (int i = 0; i < 2; i++)
            wmma::load_matrix_sync(a[i], &Qs[wr * 32 + i * 16][kk * 16], 48);
        #pragma unroll
        for (int j = 0; j < 4; j++)
            wmma::load_matrix_sync(bf[j], &Ks[wc * 64 + j * 16][kk * 16], 48);
        #pragma unroll
        for (int i = 0; i < 2; i++)
            #pragma unroll
            for (int j = 0; j < 4; j++) wmma::mma_sync(c[i][j], a[i], bf[j], c[i][j]);
    }
    #pragma unroll
    for (int i = 0; i < 2; i++)
        #pragma unroll
        for (int j = 0; j < 4; j++)
            #pragma unroll
            for (int e = 0; e < c[i][j].num_elements; e++) c[i][j].x[e] *= ATT_SCALE;
    __half* op = g_sattn + ((long)b * NHh + h) * Nn * Nn;
    // two-pass epilogue over column halves (Cs aliases Qs/Ks, now dead)
    #pragma unroll
    for (int half = 0; half < 2; half++) {
        __syncthreads();
        if (wc == half) {
            #pragma unroll
            for (int i = 0; i < 2; i++)
                #pragma unroll
                for (int j = 0; j < 4; j++)
                    wmma::store_matrix_sync(&Cs[wr * 32 + i * 16][j * 16], c[i][j], 68,
                                            wmma::mem_row_major);
        }
        __syncthreads();
        #pragma unroll
        for (int i2 = 0; i2 < 8; i2++) {  // 128x64 floats = 2048 float4
            int idx = tid + i2 * 256;
            int r = idx >> 4, c4 = (idx & 15) * 4;
            float4 s = *(float4*)&Cs[r][c4];
            *(__half2*)&op[(long)(n0 + r) * Nn + m0 + half * 64 + c4]     = __floats2half2_rn(s.x, s.y);
            *(__half2*)&op[(long)(n0 + r) * Nn + m0 + half * 64 + c4 + 2] = __floats2half2_rn(s.z, s.w);
        }
    }
}

__device__ __forceinline__ void mergeTriple(float& m, float& z, float& s,
                                            float mo, float zo, float so) {
    float nm = fmaxf(m, mo);
    float f1 = __expf(m - nm), f2 = __expf(mo - nm);
    z = z * f1 + zo * f2;
    s = s * f1 + so * f2;
    m = nm;
}

// warp-per-head: r = rawscore(fp16) + edge*ew + eb; softmax; probs IN-PLACE (fp16);
// edge_new cross-head; edge update; wsum.
__global__ void softmax_ednew(const float* __restrict__ exp_w, const float* __restrict__ exp_b,
                              const float* __restrict__ red_w, const float* __restrict__ red_b) {
    __shared__ float es[Nn];
    __shared__ float Ts[NHh][Nn];
    __shared__ float red3[24];
    int bn = blockIdx.x;
    int b = bn >> 10, n = bn & 1023;
    int tid = threadIdx.x;  // 256 = 8 warps
    int w = tid >> 5, lane = tid & 31;
    __half* Ab = g_sattn + (((long)b * NHh + w) * Nn + n) * Nn;  // scores in, probs out
    float* ep = g_edge + (long)b * Nn * Nn + (long)n * Nn;
    *(float4*)&es[tid * 4] = *(const float4*)&ep[tid * 4];
    __syncthreads();
    float ew = exp_w[w], eb = exp_b[w], rw = red_w[w];

    float4 r[8], e[8];
    #pragma unroll
    for (int k = 0; k < 8; k++) {
        __half2 h0 = *(const __half2*)&Ab[lane * 4 + k * 128];
        __half2 h1 = *(const __half2*)&Ab[lane * 4 + k * 128 + 2];
        float2 f0 = __half22float2(h0), f1 = __half22float2(h1);
        float4 ev = *(float4*)&es[lane * 4 + k * 128];
        r[k].x = f0.x + ev.x * ew + eb; r[k].y = f0.y + ev.y * ew + eb;
        r[k].z = f1.x + ev.z * ew + eb; r[k].w = f1.y + ev.w * ew + eb;
    }
    float M = -INFINITY;
    #pragma unroll
    for (int k = 0; k < 8; k++)
        M = fmaxf(M, fmaxf(fmaxf(r[k].x, r[k].y), fmaxf(r[k].z, r[k].w)));
    #pragma unroll
    for (int o = 16; o > 0; o >>= 1) M = fmaxf(M, __shfl_xor_sync(0xffffffffu, M, o));
    float Z = 0.f;
    #pragma unroll
    for (int k = 0; k < 8; k++) {
        e[k].x = __expf(r[k].x - M); e[k].y = __expf(r[k].y - M);
        e[k].z = __expf(r[k].z - M); e[k].w = __expf(r[k].w - M);
        Z += e[k].x + e[k].y + e[k].z + e[k].w;
    }
    #pragma unroll
    for (int o = 16; o > 0; o >>= 1) Z += __shfl_xor_sync(0xffffffffu, Z, o);
    float inv = 1.f / Z;
    #pragma unroll
    for (int k = 0; k < 8; k++) {
        float ax = e[k].x * inv, ay = e[k].y * inv, az = e[k].z * inv, aw = e[k].w * inv;
        *(__half2*)&Ab[lane * 4 + k * 128]     = __floats2half2_rn(ax, ay);
        *(__half2*)&Ab[lane * 4 + k * 128 + 2] = __floats2half2_rn(az, aw);
        float4 t;
        t.x = rw * (ax + r[k].x); t.y = rw * (ay + r[k].y);
        t.z = rw * (az + r[k].z); t.w = rw * (aw + r[k].w);
        *(float4*)&Ts[w][lane * 4 + k * 128] = t;
    }
    __syncthreads();

    float rb = red_b[0];
    float4 en = {rb, rb, rb, rb};
    #pragma unroll
    for (int h = 0; h < NHh; h++) {
        float4 t = *(float4*)&Ts[h][tid * 4];
        en.x += t.x; en.y += t.y; en.z += t.z; en.w += t.w;
    }
    float4 ec = *(float4*)&es[tid * 4];
    ec.x += en.x; ec.y += en.y; ec.z += en.z; ec.w += en.w;
    *(float4*)&ep[tid * 4] = ec;
    float m2 = fmaxf(fmaxf(en.x, en.y), fmaxf(en.z, en.w));
    float f0 = __expf(en.x - m2), f1 = __expf(en.y - m2),
          f2 = __expf(en.z - m2), f3 = __expf(en.w - m2);
    float z2 = f0 + f1 + f2 + f3;
    float s2 = f0 * en.x + f1 * en.y + f2 * en.z + f3 * en.w;
    #pragma unroll
    for (int o = 16; o > 0; o >>= 1)
        mergeTriple(m2, z2, s2,
                    __shfl_xor_sync(0xffffffffu, m2, o),
                    __shfl_xor_sync(0xffffffffu, z2, o),
                    __shfl_xor_sync(0xffffffffu, s2, o));
    if (lane == 0) { red3[w * 3] = m2; red3[w * 3 + 1] = z2; red3[w * 3 + 2] = s2; }
    __syncthreads();
    if (tid < 32) {
        float mm = (lane < 8) ? red3[lane * 3]     : -INFINITY;
        float zz = (lane < 8) ? red3[lane * 3 + 1] : 0.f;
        float ss = (lane < 8) ? red3[lane * 3 + 2] : 0.f;
        #pragma unroll
        for (int o = 4; o > 0; o >>= 1)
            mergeTriple(mm, zz, ss,
                        __shfl_xor_sync(0xffffffffu, mm, o),
                        __shfl_xor_sync(0xffffffffu, zz, o),
                        __shfl_xor_sync(0xffffffffu, ss, o));
        if (lane == 0) g_wsum[bn] = ss / zz;
    }
}

// AV (fp16 WMMA): node_out = P @ V + wsum. 128-row tiles, 8 warps.
__global__ void av_half(void) {
    __shared__ __half Vs[64][48];
    __shared__ float Cs[128][48];
    int bh = blockIdx.y;
    int b = bh >> 3, h = bh & 7;
    int n0 = blockIdx.x * 128;
    int tid = threadIdx.x;  // 256
    int w = tid >> 5;       // 8 warps, 16 rows each
    const __half* Ap = g_sattn + (((long)b * NHh + h) * Nn + n0) * Nn;
    const float* Vb = g_qkv + (long)b * Nn * 960 + 2 * Cc + h * DHh;
    for (int idx = tid; idx < 512; idx += 256) Vs[idx >> 3][40 + (idx & 7)] = __float2half(0.f);
    wmma::fragment<wmma::accumulator, 16, 16, 16, float> c[3];
    #pragma unroll
    for (int j = 0; j < 3; j++) wmma::fill_fragment(c[j], 0.f);
    for (int m0 = 0; m0 < Nn; m0 += 64) {
        __syncthreads();
        for (int idx = tid; idx < 640; idx += 256) {
            int r = idx / 10, c4 = (idx % 10) * 4;
            float4 v = *(const float4*)&Vb[(long)(m0 + r) * 960 + c4];
            *(__half2*)&Vs[r][c4]     = __floats2half2_rn(v.x, v.y);
            *(__half2*)&Vs[r][c4 + 2] = __floats2half2_rn(v.z, v.w);
        }
        __syncthreads();
        #pragma unroll
        for (int kk = 0; kk < 4; kk++) {
            wmma::fragment<wmma::matrix_a, 16, 16, 16, __half, wmma::row_major> a;
            wmma::load_matrix_sync(a, Ap + (long)(w * 16) * Nn + m0 + kk * 16, Nn);
            #pragma unroll
            for (int j = 0; j < 3; j++) {
                wmma::fragment<wmma::matrix_b, 16, 16, 16, __half, wmma::row_major> bf;
                wmma::load_matrix_sync(bf, &Vs[kk * 16][j * 16], 48);
                wmma::mma_sync(c[j], a, bf, c[j]);
            }
        }
    }
    __syncthreads();
    #pragma unroll
    for (int j = 0; j < 3; j++)
        wmma::store_matrix_sync(&Cs[w * 16][j * 16], c[j], 48, wmma::mem_row_major);
    __syncthreads();
    const float* wsp = g_wsum + b * Nn + n0;
    float* op = g_nodeout + ((long)b * Nn + n0) * Cc + h * DHh;
    for (int idx = tid; idx < 1280; idx += 256) {
        int r = idx / 10, c4 = (idx % 10) * 4;
        float wv = wsp[r];
        float4 v = *(float4*)&Cs[r][c4];
        v.x += wv; v.y += wv; v.z += wv; v.w += wv;
        *(float4*)&op[(long)r * Cc + c4] = v;
    }
}

static float* sym(const void* s) {
    void* p = nullptr;
    cudaGetSymbolAddress(&p, s);
    return (float*)p;
}

extern "C" void kernel_launch(void* const* d_in, const int* in_sizes, int n_in,
                              void* d_out, int out_size) {
    const float* x        = (const float*)d_in[0];
    const float* da_prior = (const float*)d_in[1];
    const float* qk_w     = (const float*)d_in[2];
    const float* fcp_w    = (const float*)d_in[3];
    const float* fcp_b    = (const float*)d_in[4];
    const float* ln1_g    = (const float*)d_in[5];
    const float* ln1_b    = (const float*)d_in[6];
    const float* gln_g    = (const float*)d_in[7];
    const float* gln_b    = (const float*)d_in[8];
    const float* qkv_w    = (const float*)d_in[9];
    const float* qkv_b    = (const float*)d_in[10];
    const float* proj_w   = (const float*)d_in[11];
    const float* proj_b   = (const float*)d_in[12];
    const float* exp_w    = (const float*)d_in[13];
    const float* exp_b    = (const float*)d_in[14];
    const float* red_w    = (const float*)d_in[15];
    const float* red_b    = (const float*)d_in[16];
    float* out = (float*)d_out;

    float* p_node    = sym(g_node);
    float* p_qk2     = sym(g_qk2);
    float* p_edge    = sym(g_edge);
    float* p_y       = sym(g_y);
    float* p_qkv     = sym(g_qkv);
    float* p_nodeout = sym(g_nodeout);

    transpose_in<<<dim3(32, 10, Bb), dim3(32, 32)>>>(x);
    gemm_half<<<dim3(10, 16, 1), 256>>>(p_node, qk_w, nullptr, p_qk2,
                                        Bb * Nn, 2 * Cc, Cc, Cc, Cc, 2 * Cc, 0, 0, 0, 1.f);
    gemm_half<<<dim3(16, 8, Bb), 256>>>(p_qk2, p_qk2 + Cc, nullptr, p_edge,
                                        Nn, Nn, Cc, 2 * Cc, 2 * Cc, Nn,
                                        (long)Nn * 2 * Cc, (long)Nn * 2 * Cc, (long)Nn * Nn,
                                        EDGE_SCALE);
    edge_softmax<<<Bb * Nn / 8, 256>>>();
    fcp_kernel<<<Bb, Cc>>>(da_prior, fcp_w, fcp_b);

    for (int l = 0; l < Ll; l++) {
        norm_kernel<<<Bb * Nn / 8, 256>>>(ln1_g + l * Cc, ln1_b + l * Cc,
                                          gln_g + l * Cc, gln_b + l * Cc);
        gemm_half<<<dim3(15, 16, 1), 256>>>(p_y, qkv_w + (long)l * 3 * Cc * Cc,
                                            qkv_b + l * 3 * Cc, p_qkv,
                                            Bb * Nn, 3 * Cc, Cc, Cc, Cc, 3 * Cc, 0, 0, 0, 1.f);
        attn_score_half<<<dim3(8, 8, Bb * NHh), 256>>>();
        softmax_ednew<<<Bb * Nn, 256>>>(exp_w + l * NHh, exp_b + l * NHh,
                                        red_w + l * NHh, red_b + l);
        av_half<<<dim3(8, Bb * NHh), 256>>>();
        gemm_half<<<dim3(5, 16, 1), 256>>>(p_nodeout, proj_w + (long)l * Cc * Cc,
                                           proj_b + l * Cc, p_node,
                                           Bb * Nn, Cc, Cc, Cc, Cc, Cc, 0, 0, 0, 1.f);
    }
    transpose_out<<<dim3(32, 10, Bb), dim3(32, 32)>>>(out);
}